// round 4
// baseline (speedup 1.0000x reference)
#include <cuda_runtime.h>

#define S_LEN 1728
#define B_SZ 2
#define E_DIM 256
#define H_NUM 8
#define P_DIM 32
#define M_ROWS (B_SZ * S_LEN)   // 3456

// Scratch (no allocations allowed)
__device__ float g_q[B_SZ * H_NUM * S_LEN * P_DIM];      // [B,H,S,P]
__device__ float g_k[B_SZ * H_NUM * S_LEN * P_DIM];
__device__ float g_v[B_SZ * H_NUM * S_LEN * P_DIM];
__device__ float g_attn[M_ROWS * E_DIM];                 // [B*S, E]

// ---------------------------------------------------------------------------
// Kernel 1: QKV projection. grid = (54, 4, 3), block = 256 (16x16, 4x4 micro)
// Output written in head-split layout [B,H,S,P].
// ---------------------------------------------------------------------------
__global__ __launch_bounds__(256) void qkv_kernel(
    const float* __restrict__ x,
    const float* __restrict__ Wq, const float* __restrict__ bq,
    const float* __restrict__ Wk, const float* __restrict__ bk,
    const float* __restrict__ Wv, const float* __restrict__ bv)
{
    __shared__ float xs[64][33];
    __shared__ float ws[32][64];

    const int tid = threadIdx.x;
    const int tx = tid & 15, ty = tid >> 4;
    const int m0 = blockIdx.x * 64;
    const int n0 = blockIdx.y * 64;
    const int z  = blockIdx.z;

    const float* W    = (z == 0) ? Wq : (z == 1) ? Wk : Wv;
    const float* bias = (z == 0) ? bq : (z == 1) ? bk : bv;
    float* dst        = (z == 0) ? g_q : (z == 1) ? g_k : g_v;

    float acc[4][4] = {};

    for (int k0 = 0; k0 < E_DIM; k0 += 32) {
        #pragma unroll
        for (int i = 0; i < 2; i++) {
            int e = tid + i * 256;
            int r = e >> 3, f4 = e & 7;
            float4 g = *(const float4*)&x[(m0 + r) * E_DIM + k0 + f4 * 4];
            xs[r][f4 * 4 + 0] = g.x; xs[r][f4 * 4 + 1] = g.y;
            xs[r][f4 * 4 + 2] = g.z; xs[r][f4 * 4 + 3] = g.w;
        }
        #pragma unroll
        for (int i = 0; i < 2; i++) {
            int e = tid + i * 256;
            int kk = e >> 4, f4 = e & 15;
            *(float4*)&ws[kk][f4 * 4] =
                *(const float4*)&W[(k0 + kk) * E_DIM + n0 + f4 * 4];
        }
        __syncthreads();
        #pragma unroll
        for (int kk = 0; kk < 32; kk++) {
            float4 bv4 = *(const float4*)&ws[kk][tx * 4];
            float bb[4] = {bv4.x, bv4.y, bv4.z, bv4.w};
            #pragma unroll
            for (int i = 0; i < 4; i++) {
                float a = xs[ty * 4 + i][kk];
                #pragma unroll
                for (int j = 0; j < 4; j++) acc[i][j] += a * bb[j];
            }
        }
        __syncthreads();
    }

    #pragma unroll
    for (int i = 0; i < 4; i++) {
        int m = m0 + ty * 4 + i;
        int b = m / S_LEN, s = m % S_LEN;
        #pragma unroll
        for (int j = 0; j < 4; j++) {
            int n = n0 + tx * 4 + j;
            int h = n >> 5, p = n & 31;
            dst[((b * H_NUM + h) * S_LEN + s) * P_DIM + p] = acc[i][j] + bias[n];
        }
    }
}

// ---------------------------------------------------------------------------
// Kernel 2: flash attention. grid = (27, 16), block = 256.
// Per block: 64 query rows of one (b,h), stream K/V in 64-row tiles,
// online softmax (no 1/sqrt(P) scaling, matching reference).
// ---------------------------------------------------------------------------
__global__ __launch_bounds__(256) void attn_kernel()
{
    __shared__ float qs[64][33];
    __shared__ float kts[32][64];   // K transposed: kts[kk][c]
    __shared__ float vs[64][32];    // vs[c][p]
    __shared__ float ss[64][65];    // scores then probabilities
    __shared__ float ms[64], ls[64], scs[64];

    const int tid = threadIdx.x;
    const int tx = tid & 15, ty = tid >> 4;
    const int bh = blockIdx.y;
    const int q0 = blockIdx.x * 64;

    const float* Qb = g_q + (size_t)bh * S_LEN * P_DIM;
    const float* Kb = g_k + (size_t)bh * S_LEN * P_DIM;
    const float* Vb = g_v + (size_t)bh * S_LEN * P_DIM;

    #pragma unroll
    for (int i = 0; i < 2; i++) {
        int e = tid + i * 256;
        int r = e >> 3, f4 = e & 7;
        float4 g = *(const float4*)&Qb[(q0 + r) * P_DIM + f4 * 4];
        qs[r][f4 * 4 + 0] = g.x; qs[r][f4 * 4 + 1] = g.y;
        qs[r][f4 * 4 + 2] = g.z; qs[r][f4 * 4 + 3] = g.w;
    }
    if (tid < 64) { ms[tid] = -1e30f; ls[tid] = 0.f; }

    float oa[4][2] = {};
    const int rsf = tid >> 2;   // softmax row (4 threads per row)
    const int seg = tid & 3;

    for (int kt = 0; kt < S_LEN / 64; kt++) {
        __syncthreads();        // protect smem reuse from previous iteration
        const int k0 = kt * 64;
        #pragma unroll
        for (int i = 0; i < 2; i++) {
            int e = tid + i * 256;
            int c = e >> 3, f4 = e & 7;
            float4 g  = *(const float4*)&Kb[(k0 + c) * P_DIM + f4 * 4];
            kts[f4 * 4 + 0][c] = g.x; kts[f4 * 4 + 1][c] = g.y;
            kts[f4 * 4 + 2][c] = g.z; kts[f4 * 4 + 3][c] = g.w;
            float4 gv = *(const float4*)&Vb[(k0 + c) * P_DIM + f4 * 4];
            *(float4*)&vs[c][f4 * 4] = gv;
        }
        __syncthreads();

        // S = Q K^T  (64x64)
        float sa[4][4] = {};
        #pragma unroll
        for (int kk = 0; kk < 32; kk++) {
            float4 bv4 = *(const float4*)&kts[kk][tx * 4];
            float bb[4] = {bv4.x, bv4.y, bv4.z, bv4.w};
            #pragma unroll
            for (int i = 0; i < 4; i++) {
                float a = qs[ty * 4 + i][kk];
                #pragma unroll
                for (int j = 0; j < 4; j++) sa[i][j] += a * bb[j];
            }
        }
        #pragma unroll
        for (int i = 0; i < 4; i++)
            #pragma unroll
            for (int j = 0; j < 4; j++)
                ss[ty * 4 + i][tx * 4 + j] = sa[i][j];
        __syncthreads();

        // online softmax: 4 threads per row, 16 cols each
        float lm = -1e30f;
        #pragma unroll
        for (int c = 0; c < 16; c++) lm = fmaxf(lm, ss[rsf][seg * 16 + c]);
        lm = fmaxf(lm, __shfl_xor_sync(0xffffffffu, lm, 1));
        lm = fmaxf(lm, __shfl_xor_sync(0xffffffffu, lm, 2));
        float mold = ms[rsf];
        float mnew = fmaxf(mold, lm);
        float ps = 0.f;
        #pragma unroll
        for (int c = 0; c < 16; c++) {
            float p = __expf(ss[rsf][seg * 16 + c] - mnew);
            ss[rsf][seg * 16 + c] = p;
            ps += p;
        }
        ps += __shfl_xor_sync(0xffffffffu, ps, 1);
        ps += __shfl_xor_sync(0xffffffffu, ps, 2);
        if (seg == 0) {
            ms[rsf]  = mnew;
            scs[rsf] = __expf(mold - mnew);
            ls[rsf]  = ls[rsf] * scs[rsf] + ps;
        }
        __syncthreads();

        // rescale running O, then O += P @ V
        #pragma unroll
        for (int i = 0; i < 4; i++) {
            float sc = scs[ty * 4 + i];
            oa[i][0] *= sc; oa[i][1] *= sc;
        }
        #pragma unroll
        for (int c = 0; c < 64; c++) {
            float b0 = vs[c][tx * 2], b1 = vs[c][tx * 2 + 1];
            #pragma unroll
            for (int i = 0; i < 4; i++) {
                float a = ss[ty * 4 + i][c];
                oa[i][0] += a * b0; oa[i][1] += a * b1;
            }
        }
    }

    const int b = bh >> 3, h = bh & 7;
    #pragma unroll
    for (int i = 0; i < 4; i++) {
        int s = q0 + ty * 4 + i;
        float inv = 1.0f / ls[ty * 4 + i];
        float* o = &g_attn[((size_t)b * S_LEN + s) * E_DIM + h * P_DIM + tx * 2];
        o[0] = oa[i][0] * inv;
        o[1] = oa[i][1] * inv;
    }
}

// ---------------------------------------------------------------------------
// Kernel 3: output projection. grid = (54, 4), block = 256.
// ---------------------------------------------------------------------------
__global__ __launch_bounds__(256) void out_kernel(
    const float* __restrict__ Wo, const float* __restrict__ bo,
    float* __restrict__ out)
{
    __shared__ float xs[64][33];
    __shared__ float ws[32][64];

    const int tid = threadIdx.x;
    const int tx = tid & 15, ty = tid >> 4;
    const int m0 = blockIdx.x * 64;
    const int n0 = blockIdx.y * 64;

    float acc[4][4] = {};

    for (int k0 = 0; k0 < E_DIM; k0 += 32) {
        #pragma unroll
        for (int i = 0; i < 2; i++) {
            int e = tid + i * 256;
            int r = e >> 3, f4 = e & 7;
            float4 g = *(const float4*)&g_attn[(size_t)(m0 + r) * E_DIM + k0 + f4 * 4];
            xs[r][f4 * 4 + 0] = g.x; xs[r][f4 * 4 + 1] = g.y;
            xs[r][f4 * 4 + 2] = g.z; xs[r][f4 * 4 + 3] = g.w;
        }
        #pragma unroll
        for (int i = 0; i < 2; i++) {
            int e = tid + i * 256;
            int kk = e >> 4, f4 = e & 15;
            *(float4*)&ws[kk][f4 * 4] =
                *(const float4*)&Wo[(k0 + kk) * E_DIM + n0 + f4 * 4];
        }
        __syncthreads();
        #pragma unroll
        for (int kk = 0; kk < 32; kk++) {
            float4 bv4 = *(const float4*)&ws[kk][tx * 4];
            float bb[4] = {bv4.x, bv4.y, bv4.z, bv4.w};
            #pragma unroll
            for (int i = 0; i < 4; i++) {
                float a = xs[ty * 4 + i][kk];
                #pragma unroll
                for (int j = 0; j < 4; j++) acc[i][j] += a * bb[j];
            }
        }
        __syncthreads();
    }

    #pragma unroll
    for (int i = 0; i < 4; i++) {
        int m = m0 + ty * 4 + i;
        #pragma unroll
        for (int j = 0; j < 4; j++) {
            int n = n0 + tx * 4 + j;
            out[(size_t)m * E_DIM + n] = acc[i][j] + bo[n];
        }
    }
}

extern "C" void kernel_launch(void* const* d_in, const int* in_sizes, int n_in,
                              void* d_out, int out_size)
{
    const float* x  = (const float*)d_in[0];
    const float* Wq = (const float*)d_in[1];
    const float* bq = (const float*)d_in[2];
    const float* Wk = (const float*)d_in[3];
    const float* bk = (const float*)d_in[4];
    const float* Wv = (const float*)d_in[5];
    const float* bv = (const float*)d_in[6];
    const float* Wo = (const float*)d_in[7];
    const float* bo = (const float*)d_in[8];
    float* out = (float*)d_out;

    qkv_kernel<<<dim3(54, 4, 3), 256>>>(x, Wq, bq, Wk, bk, Wv, bv);
    attn_kernel<<<dim3(27, 16), 256>>>();
    out_kernel<<<dim3(54, 4), 256>>>(Wo, bo, out);
}

// round 6
// speedup vs baseline: 1.7508x; 1.7508x over previous
#include <cuda_runtime.h>
#include <cuda_bf16.h>
#include <cstdint>

#define S_LEN 1728
#define B_SZ 2
#define E_DIM 256
#define H_NUM 8
#define P_DIM 32
#define M_ROWS (B_SZ * S_LEN)   // 3456

#define QT 128                  // q rows per block
#define KN 64                   // keys per tile
#define NKT (S_LEN / KN)        // 27

// Scratch (no allocations allowed)
__device__ float g_q[B_SZ * H_NUM * S_LEN * P_DIM];      // [B,H,S,P]
__device__ float g_k[B_SZ * H_NUM * S_LEN * P_DIM];
__device__ float g_v[B_SZ * H_NUM * S_LEN * P_DIM];
__device__ float g_attn[M_ROWS * E_DIM];                 // [B*S, E]

// ---------------------------------------------------------------------------
// warp-level mma.sync helpers (sm_80+ ISA, works at target sm_103)
// ---------------------------------------------------------------------------
__device__ __forceinline__ void mma16816(float c[4],
    uint32_t a0, uint32_t a1, uint32_t a2, uint32_t a3,
    uint32_t b0, uint32_t b1)
{
    asm volatile(
        "mma.sync.aligned.m16n8k16.row.col.f32.bf16.bf16.f32 "
        "{%0,%1,%2,%3}, {%4,%5,%6,%7}, {%8,%9}, {%0,%1,%2,%3};"
        : "+f"(c[0]), "+f"(c[1]), "+f"(c[2]), "+f"(c[3])
        : "r"(a0), "r"(a1), "r"(a2), "r"(a3), "r"(b0), "r"(b1));
}

__device__ __forceinline__ uint32_t pack_bf16(float e0, float e1) {
    // low 16 bits = e0 (lower col index), high 16 = e1
    return ((uint32_t)__bfloat16_as_ushort(__float2bfloat16(e1)) << 16) |
           (uint32_t)__bfloat16_as_ushort(__float2bfloat16(e0));
}

// ---------------------------------------------------------------------------
// Kernel 1: QKV projection (fp32 SIMT). grid = (54, 4, 3), block = 256.
// ---------------------------------------------------------------------------
__global__ __launch_bounds__(256) void qkv_kernel(
    const float* __restrict__ x,
    const float* __restrict__ Wq, const float* __restrict__ bq,
    const float* __restrict__ Wk, const float* __restrict__ bk,
    const float* __restrict__ Wv, const float* __restrict__ bv)
{
    __shared__ float xs[64][33];
    __shared__ float ws[32][64];

    const int tid = threadIdx.x;
    const int tx = tid & 15, ty = tid >> 4;
    const int m0 = blockIdx.x * 64;
    const int n0 = blockIdx.y * 64;
    const int z  = blockIdx.z;

    const float* W    = (z == 0) ? Wq : (z == 1) ? Wk : Wv;
    const float* bias = (z == 0) ? bq : (z == 1) ? bk : bv;
    float* dst        = (z == 0) ? g_q : (z == 1) ? g_k : g_v;

    float acc[4][4] = {};

    for (int k0 = 0; k0 < E_DIM; k0 += 32) {
        #pragma unroll
        for (int i = 0; i < 2; i++) {
            int e = tid + i * 256;
            int r = e >> 3, f4 = e & 7;
            float4 g = *(const float4*)&x[(m0 + r) * E_DIM + k0 + f4 * 4];
            xs[r][f4 * 4 + 0] = g.x; xs[r][f4 * 4 + 1] = g.y;
            xs[r][f4 * 4 + 2] = g.z; xs[r][f4 * 4 + 3] = g.w;
        }
        #pragma unroll
        for (int i = 0; i < 2; i++) {
            int e = tid + i * 256;
            int kk = e >> 4, f4 = e & 15;
            *(float4*)&ws[kk][f4 * 4] =
                *(const float4*)&W[(k0 + kk) * E_DIM + n0 + f4 * 4];
        }
        __syncthreads();
        #pragma unroll
        for (int kk = 0; kk < 32; kk++) {
            float4 bv4 = *(const float4*)&ws[kk][tx * 4];
            float bb[4] = {bv4.x, bv4.y, bv4.z, bv4.w};
            #pragma unroll
            for (int i = 0; i < 4; i++) {
                float a = xs[ty * 4 + i][kk];
                #pragma unroll
                for (int j = 0; j < 4; j++) acc[i][j] += a * bb[j];
            }
        }
        __syncthreads();
    }

    #pragma unroll
    for (int i = 0; i < 4; i++) {
        int m = m0 + ty * 4 + i;
        int b = m / S_LEN, s = m % S_LEN;
        #pragma unroll
        for (int j = 0; j < 4; j++) {
            int n = n0 + tx * 4 + j;
            int h = n >> 5, p = n & 31;
            dst[((b * H_NUM + h) * S_LEN + s) * P_DIM + p] = acc[i][j] + bias[n];
        }
    }
}

// ---------------------------------------------------------------------------
// Kernel 2: flash attention on tensor cores via mma.sync, bf16-split 3-MMA
// fp32 emulation. grid = (14, 16), block = 256 (8 warps, warp = 16 q rows).
// Unnormalized exp accumulation (|scores| <~ 34, exp fits fp32 easily).
// ---------------------------------------------------------------------------
__global__ __launch_bounds__(256, 2) void attn_mma_kernel()
{
    __shared__ __nv_bfloat16 Qh[QT][40], Ql[QT][40];   // padded: banks 20g+tig
    __shared__ __nv_bfloat16 Kh[KN][40], Kl[KN][40];
    __shared__ __nv_bfloat16 Vth[P_DIM][72], Vtl[P_DIM][72]; // banks 4g+tig

    const int tid  = threadIdx.x;
    const int warp = tid >> 5, lane = tid & 31;
    const int g    = lane >> 2, tig = lane & 3;
    const int woff = warp * 16;
    const int bh   = blockIdx.y;
    const int q0   = blockIdx.x * QT;

    const float* Qb = g_q + (size_t)bh * S_LEN * P_DIM;
    const float* Kb = g_k + (size_t)bh * S_LEN * P_DIM;
    const float* Vb = g_v + (size_t)bh * S_LEN * P_DIM;

    // ---- load + split Q tile (zero-pad rows >= S) ----
    for (int i = tid; i < QT * 8; i += 256) {
        int r = i >> 3, c4 = (i & 7) * 4;
        float4 v = (q0 + r < S_LEN)
                 ? *(const float4*)&Qb[(size_t)(q0 + r) * P_DIM + c4]
                 : make_float4(0.f, 0.f, 0.f, 0.f);
        float vv[4] = {v.x, v.y, v.z, v.w};
        #pragma unroll
        for (int j = 0; j < 4; j++) {
            __nv_bfloat16 h = __float2bfloat16(vv[j]);
            Qh[r][c4 + j] = h;
            Ql[r][c4 + j] = __float2bfloat16(vv[j] - __bfloat162float(h));
        }
    }
    __syncthreads();

    // ---- Q fragments (persist in registers): 2 ksteps x 4 regs, hi+lo ----
    uint32_t qh[2][4], ql[2][4];
    #pragma unroll
    for (int ks = 0; ks < 2; ks++) {
        int p0 = ks * 16 + 2 * tig;
        qh[ks][0] = *(const uint32_t*)&Qh[woff + g][p0];
        qh[ks][1] = *(const uint32_t*)&Qh[woff + 8 + g][p0];
        qh[ks][2] = *(const uint32_t*)&Qh[woff + g][p0 + 8];
        qh[ks][3] = *(const uint32_t*)&Qh[woff + 8 + g][p0 + 8];
        ql[ks][0] = *(const uint32_t*)&Ql[woff + g][p0];
        ql[ks][1] = *(const uint32_t*)&Ql[woff + 8 + g][p0];
        ql[ks][2] = *(const uint32_t*)&Ql[woff + g][p0 + 8];
        ql[ks][3] = *(const uint32_t*)&Ql[woff + 8 + g][p0 + 8];
    }

    float o[4][4] = {};           // O fragments: 4 n-tiles of p (16x32)
    float l0 = 0.f, l1 = 0.f;     // row sums (rows g, g+8)

    for (int kt = 0; kt < NKT; kt++) {
        const int k0 = kt * KN;
        __syncthreads();  // previous compute done before overwrite

        // ---- load + split K tile [key][p] ----
        for (int i = tid; i < KN * 8; i += 256) {
            int r = i >> 3, c4 = (i & 7) * 4;
            float4 v = *(const float4*)&Kb[(size_t)(k0 + r) * P_DIM + c4];
            float vv[4] = {v.x, v.y, v.z, v.w};
            #pragma unroll
            for (int j = 0; j < 4; j++) {
                __nv_bfloat16 h = __float2bfloat16(vv[j]);
                Kh[r][c4 + j] = h;
                Kl[r][c4 + j] = __float2bfloat16(vv[j] - __bfloat162float(h));
            }
        }
        // ---- load + split + transpose V tile -> Vt[p][key] ----
        for (int i = tid; i < KN * 8; i += 256) {
            int t = i >> 3, p4 = (i & 7) * 4;
            float4 v = *(const float4*)&Vb[(size_t)(k0 + t) * P_DIM + p4];
            float vv[4] = {v.x, v.y, v.z, v.w};
            #pragma unroll
            for (int j = 0; j < 4; j++) {
                __nv_bfloat16 h = __float2bfloat16(vv[j]);
                Vth[p4 + j][t] = h;
                Vtl[p4 + j][t] = __float2bfloat16(vv[j] - __bfloat162float(h));
            }
        }
        __syncthreads();

        // ---- scores (16x64) per warp: 8 n-tiles, exp, pack P fragments ----
        uint32_t phi01[8], phi23[8], plo01[8], plo23[8];
        #pragma unroll
        for (int nt = 0; nt < 8; nt++) {
            float c[4] = {0.f, 0.f, 0.f, 0.f};
            const int key = 8 * nt + g;
            #pragma unroll
            for (int ks = 0; ks < 2; ks++) {
                int p0 = ks * 16 + 2 * tig;
                uint32_t b0h = *(const uint32_t*)&Kh[key][p0];
                uint32_t b1h = *(const uint32_t*)&Kh[key][p0 + 8];
                uint32_t b0l = *(const uint32_t*)&Kl[key][p0];
                uint32_t b1l = *(const uint32_t*)&Kl[key][p0 + 8];
                mma16816(c, qh[ks][0], qh[ks][1], qh[ks][2], qh[ks][3], b0h, b1h);
                mma16816(c, ql[ks][0], ql[ks][1], ql[ks][2], ql[ks][3], b0h, b1h);
                mma16816(c, qh[ks][0], qh[ks][1], qh[ks][2], qh[ks][3], b0l, b1l);
            }
            float e0 = __expf(c[0]);
            float e1 = __expf(c[1]);
            float e2 = __expf(c[2]);
            float e3 = __expf(c[3]);
            l0 += e0 + e1;
            l1 += e2 + e3;
            // split P into bf16 hi/lo fragments (C layout == A layout pairs)
            __nv_bfloat16 h0 = __float2bfloat16(e0), h1 = __float2bfloat16(e1);
            __nv_bfloat16 h2 = __float2bfloat16(e2), h3 = __float2bfloat16(e3);
            phi01[nt] = ((uint32_t)__bfloat16_as_ushort(h1) << 16) |
                        (uint32_t)__bfloat16_as_ushort(h0);
            phi23[nt] = ((uint32_t)__bfloat16_as_ushort(h3) << 16) |
                        (uint32_t)__bfloat16_as_ushort(h2);
            plo01[nt] = pack_bf16(e0 - __bfloat162float(h0), e1 - __bfloat162float(h1));
            plo23[nt] = pack_bf16(e2 - __bfloat162float(h2), e3 - __bfloat162float(h3));
        }

        // ---- PV: O(16x32) += P(16x64) @ V(64x32) ----
        #pragma unroll
        for (int n = 0; n < 4; n++) {
            const int prow = 8 * n + g;
            #pragma unroll
            for (int ks = 0; ks < 4; ks++) {
                int kb = ks * 16 + 2 * tig;
                uint32_t b0h = *(const uint32_t*)&Vth[prow][kb];
                uint32_t b1h = *(const uint32_t*)&Vth[prow][kb + 8];
                uint32_t b0l = *(const uint32_t*)&Vtl[prow][kb];
                uint32_t b1l = *(const uint32_t*)&Vtl[prow][kb + 8];
                uint32_t a0 = phi01[2 * ks], a1 = phi23[2 * ks];
                uint32_t a2 = phi01[2 * ks + 1], a3 = phi23[2 * ks + 1];
                mma16816(o[n], a0, a1, a2, a3, b0h, b1h);
                mma16816(o[n], a0, a1, a2, a3, b0l, b1l);
                mma16816(o[n], plo01[2 * ks], plo23[2 * ks],
                               plo01[2 * ks + 1], plo23[2 * ks + 1], b0h, b1h);
            }
        }
    }

    // ---- reduce row sums across the quad (lanes 4g..4g+3 share rows) ----
    l0 += __shfl_xor_sync(0xffffffffu, l0, 1);
    l0 += __shfl_xor_sync(0xffffffffu, l0, 2);
    l1 += __shfl_xor_sync(0xffffffffu, l1, 1);
    l1 += __shfl_xor_sync(0xffffffffu, l1, 2);
    const float inv0 = 1.0f / l0;
    const float inv1 = 1.0f / l1;

    // ---- store O (normalized) ----
    const int b = bh >> 3, h = bh & 7;
    const int r0 = q0 + woff + g;
    const int r1 = r0 + 8;
    #pragma unroll
    for (int n = 0; n < 4; n++) {
        int p = 8 * n + 2 * tig;
        if (r0 < S_LEN) {
            float2 v = make_float2(o[n][0] * inv0, o[n][1] * inv0);
            *(float2*)&g_attn[((size_t)b * S_LEN + r0) * E_DIM + h * P_DIM + p] = v;
        }
        if (r1 < S_LEN) {
            float2 v = make_float2(o[n][2] * inv1, o[n][3] * inv1);
            *(float2*)&g_attn[((size_t)b * S_LEN + r1) * E_DIM + h * P_DIM + p] = v;
        }
    }
}

// ---------------------------------------------------------------------------
// Kernel 3: output projection (fp32 SIMT). grid = (54, 4), block = 256.
// ---------------------------------------------------------------------------
__global__ __launch_bounds__(256) void out_kernel(
    const float* __restrict__ Wo, const float* __restrict__ bo,
    float* __restrict__ out)
{
    __shared__ float xs[64][33];
    __shared__ float ws[32][64];

    const int tid = threadIdx.x;
    const int tx = tid & 15, ty = tid >> 4;
    const int m0 = blockIdx.x * 64;
    const int n0 = blockIdx.y * 64;

    float acc[4][4] = {};

    for (int k0 = 0; k0 < E_DIM; k0 += 32) {
        #pragma unroll
        for (int i = 0; i < 2; i++) {
            int e = tid + i * 256;
            int r = e >> 3, f4 = e & 7;
            float4 g = *(const float4*)&g_attn[(size_t)(m0 + r) * E_DIM + k0 + f4 * 4];
            xs[r][f4 * 4 + 0] = g.x; xs[r][f4 * 4 + 1] = g.y;
            xs[r][f4 * 4 + 2] = g.z; xs[r][f4 * 4 + 3] = g.w;
        }
        #pragma unroll
        for (int i = 0; i < 2; i++) {
            int e = tid + i * 256;
            int kk = e >> 4, f4 = e & 15;
            *(float4*)&ws[kk][f4 * 4] =
                *(const float4*)&Wo[(k0 + kk) * E_DIM + n0 + f4 * 4];
        }
        __syncthreads();
        #pragma unroll
        for (int kk = 0; kk < 32; kk++) {
            float4 bv4 = *(const float4*)&ws[kk][tx * 4];
            float bb[4] = {bv4.x, bv4.y, bv4.z, bv4.w};
            #pragma unroll
            for (int i = 0; i < 4; i++) {
                float a = xs[ty * 4 + i][kk];
                #pragma unroll
                for (int j = 0; j < 4; j++) acc[i][j] += a * bb[j];
            }
        }
        __syncthreads();
    }

    #pragma unroll
    for (int i = 0; i < 4; i++) {
        int m = m0 + ty * 4 + i;
        #pragma unroll
        for (int j = 0; j < 4; j++) {
            int n = n0 + tx * 4 + j;
            out[(size_t)m * E_DIM + n] = acc[i][j] + bo[n];
        }
    }
}

extern "C" void kernel_launch(void* const* d_in, const int* in_sizes, int n_in,
                              void* d_out, int out_size)
{
    const float* x  = (const float*)d_in[0];
    const float* Wq = (const float*)d_in[1];
    const float* bq = (const float*)d_in[2];
    const float* Wk = (const float*)d_in[3];
    const float* bk = (const float*)d_in[4];
    const float* Wv = (const float*)d_in[5];
    const float* bv = (const float*)d_in[6];
    const float* Wo = (const float*)d_in[7];
    const float* bo = (const float*)d_in[8];
    float* out = (float*)d_out;

    qkv_kernel<<<dim3(54, 4, 3), 256>>>(x, Wq, bq, Wk, bk, Wv, bv);
    attn_mma_kernel<<<dim3(14, 16), 256>>>();
    out_kernel<<<dim3(54, 4), 256>>>(Wo, bo, out);
}

// round 8
// speedup vs baseline: 2.0182x; 1.1527x over previous
#include <cuda_runtime.h>
#include <cuda_bf16.h>
#include <cstdint>

#define S_LEN 1728
#define B_SZ 2
#define E_DIM 256
#define H_NUM 8
#define P_DIM 32
#define M_ROWS (B_SZ * S_LEN)   // 3456

#define QT 128                  // q rows per block (attn)
#define KN 64                   // keys per tile (attn)
#define NKT (S_LEN / KN)        // 27

// Scratch (no allocations allowed)
__device__ float g_q[B_SZ * H_NUM * S_LEN * P_DIM];      // [B,H,S,P]
__device__ float g_k[B_SZ * H_NUM * S_LEN * P_DIM];
__device__ float g_v[B_SZ * H_NUM * S_LEN * P_DIM];

// split-bf16 operand scratch
__device__ __align__(16) __nv_bfloat16 g_xh[M_ROWS * E_DIM];
__device__ __align__(16) __nv_bfloat16 g_xl[M_ROWS * E_DIM];
__device__ __align__(16) __nv_bfloat16 g_wth[4 * E_DIM * E_DIM];  // Wt[n][k], z=q,k,v,o
__device__ __align__(16) __nv_bfloat16 g_wtl[4 * E_DIM * E_DIM];
__device__ __align__(16) __nv_bfloat16 g_oh[M_ROWS * E_DIM];      // attn out hi
__device__ __align__(16) __nv_bfloat16 g_ol[M_ROWS * E_DIM];      // attn out lo

// ---------------------------------------------------------------------------
// warp-level mma.sync helpers (sm_80+ ISA, compiles at target sm_103)
// ---------------------------------------------------------------------------
__device__ __forceinline__ void mma16816(float c[4],
    uint32_t a0, uint32_t a1, uint32_t a2, uint32_t a3,
    uint32_t b0, uint32_t b1)
{
    asm volatile(
        "mma.sync.aligned.m16n8k16.row.col.f32.bf16.bf16.f32 "
        "{%0,%1,%2,%3}, {%4,%5,%6,%7}, {%8,%9}, {%0,%1,%2,%3};"
        : "+f"(c[0]), "+f"(c[1]), "+f"(c[2]), "+f"(c[3])
        : "r"(a0), "r"(a1), "r"(a2), "r"(a3), "r"(b0), "r"(b1));
}

__device__ __forceinline__ uint32_t pack_bf16(float e0, float e1) {
    return ((uint32_t)__bfloat16_as_ushort(__float2bfloat16(e1)) << 16) |
           (uint32_t)__bfloat16_as_ushort(__float2bfloat16(e0));
}

__device__ __forceinline__ void split2(float v, __nv_bfloat16& h, __nv_bfloat16& l) {
    h = __float2bfloat16(v);
    l = __float2bfloat16(v - __bfloat162float(h));
}

// ---------------------------------------------------------------------------
// Prep 1: split x -> g_xh/g_xl. grid 864, block 256 (4 floats/thread).
// ---------------------------------------------------------------------------
__global__ __launch_bounds__(256) void prep_x_kernel(const float* __restrict__ x)
{
    int i = (blockIdx.x * 256 + threadIdx.x) * 4;
    float4 v = *(const float4*)&x[i];
    __nv_bfloat16 h0, h1, h2, h3, l0, l1, l2, l3;
    split2(v.x, h0, l0); split2(v.y, h1, l1);
    split2(v.z, h2, l2); split2(v.w, h3, l3);
    uint2 hi, lo;
    hi.x = ((uint32_t)__bfloat16_as_ushort(h1) << 16) | __bfloat16_as_ushort(h0);
    hi.y = ((uint32_t)__bfloat16_as_ushort(h3) << 16) | __bfloat16_as_ushort(h2);
    lo.x = ((uint32_t)__bfloat16_as_ushort(l1) << 16) | __bfloat16_as_ushort(l0);
    lo.y = ((uint32_t)__bfloat16_as_ushort(l3) << 16) | __bfloat16_as_ushort(l2);
    *(uint2*)&g_xh[i] = hi;
    *(uint2*)&g_xl[i] = lo;
}

// ---------------------------------------------------------------------------
// Prep 2: transpose + split weights -> g_wth/g_wtl (Wt[n][k] = W[k][n]).
// grid (8, 8, 4) of 32x32 tiles, block 256.
// ---------------------------------------------------------------------------
__global__ __launch_bounds__(256) void prep_w_kernel(
    const float* __restrict__ Wq, const float* __restrict__ Wk,
    const float* __restrict__ Wv, const float* __restrict__ Wo)
{
    __shared__ float s[32][33];
    const int z = blockIdx.z;
    const float* W = (z == 0) ? Wq : (z == 1) ? Wk : (z == 2) ? Wv : Wo;
    const int k0 = blockIdx.x * 32, n0 = blockIdx.y * 32;
    const int c = threadIdx.x & 31, r0 = threadIdx.x >> 5;
    #pragma unroll
    for (int i = 0; i < 4; i++) {
        int r = r0 + i * 8;
        s[r][c] = W[(k0 + r) * E_DIM + n0 + c];
    }
    __syncthreads();
    #pragma unroll
    for (int i = 0; i < 4; i++) {
        int r = r0 + i * 8;                 // n offset
        float v = s[c][r];                  // = W[k0+c][n0+r]
        __nv_bfloat16 h, l; split2(v, h, l);
        size_t idx = (size_t)z * E_DIM * E_DIM + (size_t)(n0 + r) * E_DIM + k0 + c;
        g_wth[idx] = h;
        g_wtl[idx] = l;
    }
}

// ---------------------------------------------------------------------------
// Kernel 1: QKV projection on tensor cores (bf16-split 3-MMA).
// grid (27, 4, 3), block 256 (8 warps = 4M x 2N; warp tile 32x32).
// C[128,64] = x[128,256] @ W[256,64]; writes head-split [B,H,S,P].
// ---------------------------------------------------------------------------
__global__ __launch_bounds__(256) void qkv_mma_kernel(
    const float* __restrict__ bq, const float* __restrict__ bk,
    const float* __restrict__ bv)
{
    __shared__ __nv_bfloat16 Ah[128][40], Al[128][40];
    __shared__ __nv_bfloat16 Bh[64][40], Bl[64][40];

    const int tid = threadIdx.x;
    const int warp = tid >> 5, lane = tid & 31;
    const int g = lane >> 2, tig = lane & 3;
    const int wm = warp >> 1, wn = warp & 1;
    const int m0 = blockIdx.x * 128;
    const int n0 = blockIdx.y * 64;
    const int z  = blockIdx.z;

    const __nv_bfloat16* wth = g_wth + (size_t)z * E_DIM * E_DIM;
    const __nv_bfloat16* wtl = g_wtl + (size_t)z * E_DIM * E_DIM;
    const float* bias = (z == 0) ? bq : (z == 1) ? bk : bv;
    float* dst        = (z == 0) ? g_q : (z == 1) ? g_k : g_v;

    float c[2][4][4] = {};

    for (int k0 = 0; k0 < E_DIM; k0 += 32) {
        // load A tile (128 x 32 bf16 hi/lo), 512 uint4 total
        #pragma unroll
        for (int i = 0; i < 2; i++) {
            int e = tid + i * 256;
            int r = e >> 2, cc = (e & 3) * 8;
            *(uint4*)&Ah[r][cc] = *(const uint4*)&g_xh[(size_t)(m0 + r) * E_DIM + k0 + cc];
            *(uint4*)&Al[r][cc] = *(const uint4*)&g_xl[(size_t)(m0 + r) * E_DIM + k0 + cc];
        }
        // load B tile (Wt rows n0..n0+63, cols k0..k0+31), 256 uint4
        {
            int r = tid >> 2, cc = (tid & 3) * 8;
            *(uint4*)&Bh[r][cc] = *(const uint4*)&wth[(size_t)(n0 + r) * E_DIM + k0 + cc];
            *(uint4*)&Bl[r][cc] = *(const uint4*)&wtl[(size_t)(n0 + r) * E_DIM + k0 + cc];
        }
        __syncthreads();

        // A fragments
        uint32_t ah[2][2][4], al[2][2][4];
        #pragma unroll
        for (int mf = 0; mf < 2; mf++) {
            int r = wm * 32 + mf * 16 + g;
            #pragma unroll
            for (int ks = 0; ks < 2; ks++) {
                int p0 = ks * 16 + 2 * tig;
                ah[mf][ks][0] = *(const uint32_t*)&Ah[r][p0];
                ah[mf][ks][1] = *(const uint32_t*)&Ah[r + 8][p0];
                ah[mf][ks][2] = *(const uint32_t*)&Ah[r][p0 + 8];
                ah[mf][ks][3] = *(const uint32_t*)&Ah[r + 8][p0 + 8];
                al[mf][ks][0] = *(const uint32_t*)&Al[r][p0];
                al[mf][ks][1] = *(const uint32_t*)&Al[r + 8][p0];
                al[mf][ks][2] = *(const uint32_t*)&Al[r][p0 + 8];
                al[mf][ks][3] = *(const uint32_t*)&Al[r + 8][p0 + 8];
            }
        }
        // B fragments + MMAs
        #pragma unroll
        for (int nf = 0; nf < 4; nf++) {
            int col = wn * 32 + nf * 8 + g;
            uint32_t bh[2][2], bl[2][2];
            #pragma unroll
            for (int ks = 0; ks < 2; ks++) {
                int p0 = ks * 16 + 2 * tig;
                bh[ks][0] = *(const uint32_t*)&Bh[col][p0];
                bh[ks][1] = *(const uint32_t*)&Bh[col][p0 + 8];
                bl[ks][0] = *(const uint32_t*)&Bl[col][p0];
                bl[ks][1] = *(const uint32_t*)&Bl[col][p0 + 8];
            }
            #pragma unroll
            for (int mf = 0; mf < 2; mf++) {
                #pragma unroll
                for (int ks = 0; ks < 2; ks++) {
                    mma16816(c[mf][nf], ah[mf][ks][0], ah[mf][ks][1],
                             ah[mf][ks][2], ah[mf][ks][3], bh[ks][0], bh[ks][1]);
                    mma16816(c[mf][nf], al[mf][ks][0], al[mf][ks][1],
                             al[mf][ks][2], al[mf][ks][3], bh[ks][0], bh[ks][1]);
                    mma16816(c[mf][nf], ah[mf][ks][0], ah[mf][ks][1],
                             ah[mf][ks][2], ah[mf][ks][3], bl[ks][0], bl[ks][1]);
                }
            }
        }
        __syncthreads();
    }

    // epilogue: + bias, head-split store
    #pragma unroll
    for (int mf = 0; mf < 2; mf++) {
        int r0 = m0 + wm * 32 + mf * 16 + g;
        int r1 = r0 + 8;
        #pragma unroll
        for (int nf = 0; nf < 4; nf++) {
            int n = n0 + wn * 32 + nf * 8 + 2 * tig;
            int h = n >> 5, p = n & 31;
            float b0 = bias[n], b1 = bias[n + 1];
            {
                int bb = r0 / S_LEN, s = r0 % S_LEN;
                float2 v = make_float2(c[mf][nf][0] + b0, c[mf][nf][1] + b1);
                *(float2*)&dst[((bb * H_NUM + h) * S_LEN + s) * P_DIM + p] = v;
            }
            {
                int bb = r1 / S_LEN, s = r1 % S_LEN;
                float2 v = make_float2(c[mf][nf][2] + b0, c[mf][nf][3] + b1);
                *(float2*)&dst[((bb * H_NUM + h) * S_LEN + s) * P_DIM + p] = v;
            }
        }
    }
}

// ---------------------------------------------------------------------------
// Kernel 2: flash attention on tensor cores via mma.sync, bf16-split 3-MMA.
// grid = (14, 16), block = 256 (8 warps, warp = 16 q rows).
// Unnormalized exp accumulation. Epilogue writes split-bf16 O (g_oh/g_ol).
// ---------------------------------------------------------------------------
__global__ __launch_bounds__(256, 2) void attn_mma_kernel()
{
    __shared__ __nv_bfloat16 Qh[QT][40], Ql[QT][40];
    __shared__ __nv_bfloat16 Kh[KN][40], Kl[KN][40];
    __shared__ __nv_bfloat16 Vth[P_DIM][72], Vtl[P_DIM][72];

    const int tid  = threadIdx.x;
    const int warp = tid >> 5, lane = tid & 31;
    const int g    = lane >> 2, tig = lane & 3;
    const int woff = warp * 16;
    const int bh   = blockIdx.y;
    const int q0   = blockIdx.x * QT;

    const float* Qb = g_q + (size_t)bh * S_LEN * P_DIM;
    const float* Kb = g_k + (size_t)bh * S_LEN * P_DIM;
    const float* Vb = g_v + (size_t)bh * S_LEN * P_DIM;

    for (int i = tid; i < QT * 8; i += 256) {
        int r = i >> 3, c4 = (i & 7) * 4;
        float4 v = (q0 + r < S_LEN)
                 ? *(const float4*)&Qb[(size_t)(q0 + r) * P_DIM + c4]
                 : make_float4(0.f, 0.f, 0.f, 0.f);
        float vv[4] = {v.x, v.y, v.z, v.w};
        #pragma unroll
        for (int j = 0; j < 4; j++) {
            __nv_bfloat16 h, l; split2(vv[j], h, l);
            Qh[r][c4 + j] = h; Ql[r][c4 + j] = l;
        }
    }
    __syncthreads();

    uint32_t qh[2][4], ql[2][4];
    #pragma unroll
    for (int ks = 0; ks < 2; ks++) {
        int p0 = ks * 16 + 2 * tig;
        qh[ks][0] = *(const uint32_t*)&Qh[woff + g][p0];
        qh[ks][1] = *(const uint32_t*)&Qh[woff + 8 + g][p0];
        qh[ks][2] = *(const uint32_t*)&Qh[woff + g][p0 + 8];
        qh[ks][3] = *(const uint32_t*)&Qh[woff + 8 + g][p0 + 8];
        ql[ks][0] = *(const uint32_t*)&Ql[woff + g][p0];
        ql[ks][1] = *(const uint32_t*)&Ql[woff + 8 + g][p0];
        ql[ks][2] = *(const uint32_t*)&Ql[woff + g][p0 + 8];
        ql[ks][3] = *(const uint32_t*)&Ql[woff + 8 + g][p0 + 8];
    }

    float o[4][4] = {};
    float l0 = 0.f, l1 = 0.f;

    for (int kt = 0; kt < NKT; kt++) {
        const int k0 = kt * KN;
        __syncthreads();

        for (int i = tid; i < KN * 8; i += 256) {
            int r = i >> 3, c4 = (i & 7) * 4;
            float4 v = *(const float4*)&Kb[(size_t)(k0 + r) * P_DIM + c4];
            float vv[4] = {v.x, v.y, v.z, v.w};
            #pragma unroll
            for (int j = 0; j < 4; j++) {
                __nv_bfloat16 h, l; split2(vv[j], h, l);
                Kh[r][c4 + j] = h; Kl[r][c4 + j] = l;
            }
        }
        for (int i = tid; i < KN * 8; i += 256) {
            int t = i >> 3, p4 = (i & 7) * 4;
            float4 v = *(const float4*)&Vb[(size_t)(k0 + t) * P_DIM + p4];
            float vv[4] = {v.x, v.y, v.z, v.w};
            #pragma unroll
            for (int j = 0; j < 4; j++) {
                __nv_bfloat16 h, l; split2(vv[j], h, l);
                Vth[p4 + j][t] = h; Vtl[p4 + j][t] = l;
            }
        }
        __syncthreads();

        uint32_t phi01[8], phi23[8], plo01[8], plo23[8];
        #pragma unroll
        for (int nt = 0; nt < 8; nt++) {
            float c[4] = {0.f, 0.f, 0.f, 0.f};
            const int key = 8 * nt + g;
            #pragma unroll
            for (int ks = 0; ks < 2; ks++) {
                int p0 = ks * 16 + 2 * tig;
                uint32_t b0h = *(const uint32_t*)&Kh[key][p0];
                uint32_t b1h = *(const uint32_t*)&Kh[key][p0 + 8];
                uint32_t b0l = *(const uint32_t*)&Kl[key][p0];
                uint32_t b1l = *(const uint32_t*)&Kl[key][p0 + 8];
                mma16816(c, qh[ks][0], qh[ks][1], qh[ks][2], qh[ks][3], b0h, b1h);
                mma16816(c, ql[ks][0], ql[ks][1], ql[ks][2], ql[ks][3], b0h, b1h);
                mma16816(c, qh[ks][0], qh[ks][1], qh[ks][2], qh[ks][3], b0l, b1l);
            }
            float e0 = __expf(c[0]);
            float e1 = __expf(c[1]);
            float e2 = __expf(c[2]);
            float e3 = __expf(c[3]);
            l0 += e0 + e1;
            l1 += e2 + e3;
            __nv_bfloat16 h0 = __float2bfloat16(e0), h1 = __float2bfloat16(e1);
            __nv_bfloat16 h2 = __float2bfloat16(e2), h3 = __float2bfloat16(e3);
            phi01[nt] = ((uint32_t)__bfloat16_as_ushort(h1) << 16) |
                        (uint32_t)__bfloat16_as_ushort(h0);
            phi23[nt] = ((uint32_t)__bfloat16_as_ushort(h3) << 16) |
                        (uint32_t)__bfloat16_as_ushort(h2);
            plo01[nt] = pack_bf16(e0 - __bfloat162float(h0), e1 - __bfloat162float(h1));
            plo23[nt] = pack_bf16(e2 - __bfloat162float(h2), e3 - __bfloat162float(h3));
        }

        #pragma unroll
        for (int n = 0; n < 4; n++) {
            const int prow = 8 * n + g;
            #pragma unroll
            for (int ks = 0; ks < 4; ks++) {
                int kb = ks * 16 + 2 * tig;
                uint32_t b0h = *(const uint32_t*)&Vth[prow][kb];
                uint32_t b1h = *(const uint32_t*)&Vth[prow][kb + 8];
                uint32_t b0l = *(const uint32_t*)&Vtl[prow][kb];
                uint32_t b1l = *(const uint32_t*)&Vtl[prow][kb + 8];
                uint32_t a0 = phi01[2 * ks], a1 = phi23[2 * ks];
                uint32_t a2 = phi01[2 * ks + 1], a3 = phi23[2 * ks + 1];
                mma16816(o[n], a0, a1, a2, a3, b0h, b1h);
                mma16816(o[n], a0, a1, a2, a3, b0l, b1l);
                mma16816(o[n], plo01[2 * ks], plo23[2 * ks],
                               plo01[2 * ks + 1], plo23[2 * ks + 1], b0h, b1h);
            }
        }
    }

    l0 += __shfl_xor_sync(0xffffffffu, l0, 1);
    l0 += __shfl_xor_sync(0xffffffffu, l0, 2);
    l1 += __shfl_xor_sync(0xffffffffu, l1, 1);
    l1 += __shfl_xor_sync(0xffffffffu, l1, 2);
    const float inv0 = 1.0f / l0;
    const float inv1 = 1.0f / l1;

    // store O split-bf16 into g_oh/g_ol [B*S, E]
    const int b = bh >> 3, h = bh & 7;
    const int r0 = q0 + woff + g;
    const int r1 = r0 + 8;
    #pragma unroll
    for (int n = 0; n < 4; n++) {
        int p = 8 * n + 2 * tig;
        if (r0 < S_LEN) {
            float v0 = o[n][0] * inv0, v1 = o[n][1] * inv0;
            __nv_bfloat16 h0, l0b, h1, l1b;
            split2(v0, h0, l0b); split2(v1, h1, l1b);
            size_t idx = ((size_t)b * S_LEN + r0) * E_DIM + h * P_DIM + p;
            *(uint32_t*)&g_oh[idx] = ((uint32_t)__bfloat16_as_ushort(h1) << 16) |
                                     __bfloat16_as_ushort(h0);
            *(uint32_t*)&g_ol[idx] = ((uint32_t)__bfloat16_as_ushort(l1b) << 16) |
                                     __bfloat16_as_ushort(l0b);
        }
        if (r1 < S_LEN) {
            float v0 = o[n][2] * inv1, v1 = o[n][3] * inv1;
            __nv_bfloat16 h0, l0b, h1, l1b;
            split2(v0, h0, l0b); split2(v1, h1, l1b);
            size_t idx = ((size_t)b * S_LEN + r1) * E_DIM + h * P_DIM + p;
            *(uint32_t*)&g_oh[idx] = ((uint32_t)__bfloat16_as_ushort(h1) << 16) |
                                     __bfloat16_as_ushort(h0);
            *(uint32_t*)&g_ol[idx] = ((uint32_t)__bfloat16_as_ushort(l1b) << 16) |
                                     __bfloat16_as_ushort(l0b);
        }
    }
}

// ---------------------------------------------------------------------------
// Kernel 3: output projection on tensor cores. grid (27, 4), block 256.
// A = g_oh/g_ol (already split), B = Wo transposed split (z=3).
// ---------------------------------------------------------------------------
__global__ __launch_bounds__(256) void out_mma_kernel(
    const float* __restrict__ bo, float* __restrict__ out)
{
    __shared__ __nv_bfloat16 Ah[128][40], Al[128][40];
    __shared__ __nv_bfloat16 Bh[64][40], Bl[64][40];

    const int tid = threadIdx.x;
    const int warp = tid >> 5, lane = tid & 31;
    const int g = lane >> 2, tig = lane & 3;
    const int wm = warp >> 1, wn = warp & 1;
    const int m0 = blockIdx.x * 128;
    const int n0 = blockIdx.y * 64;

    const __nv_bfloat16* wth = g_wth + (size_t)3 * E_DIM * E_DIM;
    const __nv_bfloat16* wtl = g_wtl + (size_t)3 * E_DIM * E_DIM;

    float c[2][4][4] = {};

    for (int k0 = 0; k0 < E_DIM; k0 += 32) {
        #pragma unroll
        for (int i = 0; i < 2; i++) {
            int e = tid + i * 256;
            int r = e >> 2, cc = (e & 3) * 8;
            *(uint4*)&Ah[r][cc] = *(const uint4*)&g_oh[(size_t)(m0 + r) * E_DIM + k0 + cc];
            *(uint4*)&Al[r][cc] = *(const uint4*)&g_ol[(size_t)(m0 + r) * E_DIM + k0 + cc];
        }
        {
            int r = tid >> 2, cc = (tid & 3) * 8;
            *(uint4*)&Bh[r][cc] = *(const uint4*)&wth[(size_t)(n0 + r) * E_DIM + k0 + cc];
            *(uint4*)&Bl[r][cc] = *(const uint4*)&wtl[(size_t)(n0 + r) * E_DIM + k0 + cc];
        }
        __syncthreads();

        uint32_t ah[2][2][4], al[2][2][4];
        #pragma unroll
        for (int mf = 0; mf < 2; mf++) {
            int r = wm * 32 + mf * 16 + g;
            #pragma unroll
            for (int ks = 0; ks < 2; ks++) {
                int p0 = ks * 16 + 2 * tig;
                ah[mf][ks][0] = *(const uint32_t*)&Ah[r][p0];
                ah[mf][ks][1] = *(const uint32_t*)&Ah[r + 8][p0];
                ah[mf][ks][2] = *(const uint32_t*)&Ah[r][p0 + 8];
                ah[mf][ks][3] = *(const uint32_t*)&Ah[r + 8][p0 + 8];
                al[mf][ks][0] = *(const uint32_t*)&Al[r][p0];
                al[mf][ks][1] = *(const uint32_t*)&Al[r + 8][p0];
                al[mf][ks][2] = *(const uint32_t*)&Al[r][p0 + 8];
                al[mf][ks][3] = *(const uint32_t*)&Al[r + 8][p0 + 8];
            }
        }
        #pragma unroll
        for (int nf = 0; nf < 4; nf++) {
            int col = wn * 32 + nf * 8 + g;
            uint32_t bh[2][2], bl[2][2];
            #pragma unroll
            for (int ks = 0; ks < 2; ks++) {
                int p0 = ks * 16 + 2 * tig;
                bh[ks][0] = *(const uint32_t*)&Bh[col][p0];
                bh[ks][1] = *(const uint32_t*)&Bh[col][p0 + 8];
                bl[ks][0] = *(const uint32_t*)&Bl[col][p0];
                bl[ks][1] = *(const uint32_t*)&Bl[col][p0 + 8];
            }
            #pragma unroll
            for (int mf = 0; mf < 2; mf++) {
                #pragma unroll
                for (int ks = 0; ks < 2; ks++) {
                    mma16816(c[mf][nf], ah[mf][ks][0], ah[mf][ks][1],
                             ah[mf][ks][2], ah[mf][ks][3], bh[ks][0], bh[ks][1]);
                    mma16816(c[mf][nf], al[mf][ks][0], al[mf][ks][1],
                             al[mf][ks][2], al[mf][ks][3], bh[ks][0], bh[ks][1]);
                    mma16816(c[mf][nf], ah[mf][ks][0], ah[mf][ks][1],
                             ah[mf][ks][2], ah[mf][ks][3], bl[ks][0], bl[ks][1]);
                }
            }
        }
        __syncthreads();
    }

    #pragma unroll
    for (int mf = 0; mf < 2; mf++) {
        int r0 = m0 + wm * 32 + mf * 16 + g;
        int r1 = r0 + 8;
        #pragma unroll
        for (int nf = 0; nf < 4; nf++) {
            int n = n0 + wn * 32 + nf * 8 + 2 * tig;
            float b0 = bo[n], b1 = bo[n + 1];
            *(float2*)&out[(size_t)r0 * E_DIM + n] =
                make_float2(c[mf][nf][0] + b0, c[mf][nf][1] + b1);
            *(float2*)&out[(size_t)r1 * E_DIM + n] =
                make_float2(c[mf][nf][2] + b0, c[mf][nf][3] + b1);
        }
    }
}

extern "C" void kernel_launch(void* const* d_in, const int* in_sizes, int n_in,
                              void* d_out, int out_size)
{
    const float* x  = (const float*)d_in[0];
    const float* Wq = (const float*)d_in[1];
    const float* bq = (const float*)d_in[2];
    const float* Wk = (const float*)d_in[3];
    const float* bk = (const float*)d_in[4];
    const float* Wv = (const float*)d_in[5];
    const float* bv = (const float*)d_in[6];
    const float* Wo = (const float*)d_in[7];
    const float* bo = (const float*)d_in[8];
    float* out = (float*)d_out;

    prep_x_kernel<<<M_ROWS * E_DIM / 1024, 256>>>(x);
    prep_w_kernel<<<dim3(8, 8, 4), 256>>>(Wq, Wk, Wv, Wo);
    qkv_mma_kernel<<<dim3(27, 4, 3), 256>>>(bq, bk, bv);
    attn_mma_kernel<<<dim3(14, 16), 256>>>();
    out_mma_kernel<<<dim3(27, 4), 256>>>(bo, out);
}

// round 9
// speedup vs baseline: 2.2934x; 1.1363x over previous
#include <cuda_runtime.h>
#include <cuda_bf16.h>
#include <cstdint>

#define S_LEN 1728
#define B_SZ 2
#define E_DIM 256
#define H_NUM 8
#define P_DIM 32
#define M_ROWS (B_SZ * S_LEN)   // 3456

#define QT 128                  // q rows per block (attn)
#define KN 64                   // keys per tile (attn)
#define NKT (S_LEN / KN)        // 27

// split-bf16 scratch (no allocations allowed)
__device__ __align__(16) __nv_bfloat16 g_qh[B_SZ * H_NUM * S_LEN * P_DIM]; // [B,H,S,P]
__device__ __align__(16) __nv_bfloat16 g_ql[B_SZ * H_NUM * S_LEN * P_DIM];
__device__ __align__(16) __nv_bfloat16 g_kh[B_SZ * H_NUM * S_LEN * P_DIM];
__device__ __align__(16) __nv_bfloat16 g_kl[B_SZ * H_NUM * S_LEN * P_DIM];
__device__ __align__(16) __nv_bfloat16 g_vth[B_SZ * H_NUM * P_DIM * S_LEN]; // [B,H,P,S]
__device__ __align__(16) __nv_bfloat16 g_vtl[B_SZ * H_NUM * P_DIM * S_LEN];
__device__ __align__(16) __nv_bfloat16 g_xh[M_ROWS * E_DIM];
__device__ __align__(16) __nv_bfloat16 g_xl[M_ROWS * E_DIM];
__device__ __align__(16) __nv_bfloat16 g_wth[4 * E_DIM * E_DIM];  // Wt[n][k], z=q,k,v,o
__device__ __align__(16) __nv_bfloat16 g_wtl[4 * E_DIM * E_DIM];
__device__ __align__(16) __nv_bfloat16 g_oh[M_ROWS * E_DIM];      // attn out hi
__device__ __align__(16) __nv_bfloat16 g_ol[M_ROWS * E_DIM];      // attn out lo

// ---------------------------------------------------------------------------
// helpers
// ---------------------------------------------------------------------------
__device__ __forceinline__ void mma16816(float c[4],
    uint32_t a0, uint32_t a1, uint32_t a2, uint32_t a3,
    uint32_t b0, uint32_t b1)
{
    asm volatile(
        "mma.sync.aligned.m16n8k16.row.col.f32.bf16.bf16.f32 "
        "{%0,%1,%2,%3}, {%4,%5,%6,%7}, {%8,%9}, {%0,%1,%2,%3};"
        : "+f"(c[0]), "+f"(c[1]), "+f"(c[2]), "+f"(c[3])
        : "r"(a0), "r"(a1), "r"(a2), "r"(a3), "r"(b0), "r"(b1));
}

__device__ __forceinline__ uint32_t smem_u32(const void* p) {
    uint32_t a;
    asm("{ .reg .u64 t; cvta.to.shared.u64 t, %1; cvt.u32.u64 %0, t; }"
        : "=r"(a) : "l"(p));
    return a;
}
__device__ __forceinline__ void cp16(uint32_t saddr, const void* g) {
    asm volatile("cp.async.cg.shared.global [%0], [%1], 16;"
                 :: "r"(saddr), "l"(g) : "memory");
}
#define CP_COMMIT() asm volatile("cp.async.commit_group;" ::: "memory")
#define CP_WAIT(N)  asm volatile("cp.async.wait_group %0;" :: "n"(N) : "memory")

__device__ __forceinline__ uint32_t pack_bf16(float e0, float e1) {
    return ((uint32_t)__bfloat16_as_ushort(__float2bfloat16(e1)) << 16) |
           (uint32_t)__bfloat16_as_ushort(__float2bfloat16(e0));
}
__device__ __forceinline__ void split2(float v, __nv_bfloat16& h, __nv_bfloat16& l) {
    h = __float2bfloat16(v);
    l = __float2bfloat16(v - __bfloat162float(h));
}

// ---------------------------------------------------------------------------
// Prep 1: split x -> g_xh/g_xl. grid 864, block 256.
// ---------------------------------------------------------------------------
__global__ __launch_bounds__(256) void prep_x_kernel(const float* __restrict__ x)
{
    int i = (blockIdx.x * 256 + threadIdx.x) * 4;
    float4 v = *(const float4*)&x[i];
    __nv_bfloat16 h0, h1, h2, h3, l0, l1, l2, l3;
    split2(v.x, h0, l0); split2(v.y, h1, l1);
    split2(v.z, h2, l2); split2(v.w, h3, l3);
    uint2 hi, lo;
    hi.x = ((uint32_t)__bfloat16_as_ushort(h1) << 16) | __bfloat16_as_ushort(h0);
    hi.y = ((uint32_t)__bfloat16_as_ushort(h3) << 16) | __bfloat16_as_ushort(h2);
    lo.x = ((uint32_t)__bfloat16_as_ushort(l1) << 16) | __bfloat16_as_ushort(l0);
    lo.y = ((uint32_t)__bfloat16_as_ushort(l3) << 16) | __bfloat16_as_ushort(l2);
    *(uint2*)&g_xh[i] = hi;
    *(uint2*)&g_xl[i] = lo;
}

// ---------------------------------------------------------------------------
// Prep 2: transpose + split weights -> g_wth/g_wtl. grid (8, 8, 4), block 256.
// ---------------------------------------------------------------------------
__global__ __launch_bounds__(256) void prep_w_kernel(
    const float* __restrict__ Wq, const float* __restrict__ Wk,
    const float* __restrict__ Wv, const float* __restrict__ Wo)
{
    __shared__ float s[32][33];
    const int z = blockIdx.z;
    const float* W = (z == 0) ? Wq : (z == 1) ? Wk : (z == 2) ? Wv : Wo;
    const int k0 = blockIdx.x * 32, n0 = blockIdx.y * 32;
    const int c = threadIdx.x & 31, r0 = threadIdx.x >> 5;
    #pragma unroll
    for (int i = 0; i < 4; i++) {
        int r = r0 + i * 8;
        s[r][c] = W[(k0 + r) * E_DIM + n0 + c];
    }
    __syncthreads();
    #pragma unroll
    for (int i = 0; i < 4; i++) {
        int r = r0 + i * 8;
        float v = s[c][r];
        __nv_bfloat16 h, l; split2(v, h, l);
        size_t idx = (size_t)z * E_DIM * E_DIM + (size_t)(n0 + r) * E_DIM + k0 + c;
        g_wth[idx] = h;
        g_wtl[idx] = l;
    }
}

// ---------------------------------------------------------------------------
// Kernel 1: QKV projection, bf16-split 3-MMA. grid (27, 4, 3), block 256.
// Epilogue splits results to bf16 hi/lo; V stored transposed [B,H,P,S].
// ---------------------------------------------------------------------------
__global__ __launch_bounds__(256) void qkv_mma_kernel(
    const float* __restrict__ bq, const float* __restrict__ bk,
    const float* __restrict__ bv)
{
    __shared__ __nv_bfloat16 Ah[128][40], Al[128][40];
    __shared__ __nv_bfloat16 Bh[64][40], Bl[64][40];

    const int tid = threadIdx.x;
    const int warp = tid >> 5, lane = tid & 31;
    const int g = lane >> 2, tig = lane & 3;
    const int wm = warp >> 1, wn = warp & 1;
    const int m0 = blockIdx.x * 128;
    const int n0 = blockIdx.y * 64;
    const int z  = blockIdx.z;

    const __nv_bfloat16* wth = g_wth + (size_t)z * E_DIM * E_DIM;
    const __nv_bfloat16* wtl = g_wtl + (size_t)z * E_DIM * E_DIM;
    const float* bias = (z == 0) ? bq : (z == 1) ? bk : bv;

    float c[2][4][4] = {};

    for (int k0 = 0; k0 < E_DIM; k0 += 32) {
        #pragma unroll
        for (int i = 0; i < 2; i++) {
            int e = tid + i * 256;
            int r = e >> 2, cc = (e & 3) * 8;
            *(uint4*)&Ah[r][cc] = *(const uint4*)&g_xh[(size_t)(m0 + r) * E_DIM + k0 + cc];
            *(uint4*)&Al[r][cc] = *(const uint4*)&g_xl[(size_t)(m0 + r) * E_DIM + k0 + cc];
        }
        {
            int r = tid >> 2, cc = (tid & 3) * 8;
            *(uint4*)&Bh[r][cc] = *(const uint4*)&wth[(size_t)(n0 + r) * E_DIM + k0 + cc];
            *(uint4*)&Bl[r][cc] = *(const uint4*)&wtl[(size_t)(n0 + r) * E_DIM + k0 + cc];
        }
        __syncthreads();

        uint32_t ah[2][2][4], al[2][2][4];
        #pragma unroll
        for (int mf = 0; mf < 2; mf++) {
            int r = wm * 32 + mf * 16 + g;
            #pragma unroll
            for (int ks = 0; ks < 2; ks++) {
                int p0 = ks * 16 + 2 * tig;
                ah[mf][ks][0] = *(const uint32_t*)&Ah[r][p0];
                ah[mf][ks][1] = *(const uint32_t*)&Ah[r + 8][p0];
                ah[mf][ks][2] = *(const uint32_t*)&Ah[r][p0 + 8];
                ah[mf][ks][3] = *(const uint32_t*)&Ah[r + 8][p0 + 8];
                al[mf][ks][0] = *(const uint32_t*)&Al[r][p0];
                al[mf][ks][1] = *(const uint32_t*)&Al[r + 8][p0];
                al[mf][ks][2] = *(const uint32_t*)&Al[r][p0 + 8];
                al[mf][ks][3] = *(const uint32_t*)&Al[r + 8][p0 + 8];
            }
        }
        #pragma unroll
        for (int nf = 0; nf < 4; nf++) {
            int col = wn * 32 + nf * 8 + g;
            uint32_t bh[2][2], bl[2][2];
            #pragma unroll
            for (int ks = 0; ks < 2; ks++) {
                int p0 = ks * 16 + 2 * tig;
                bh[ks][0] = *(const uint32_t*)&Bh[col][p0];
                bh[ks][1] = *(const uint32_t*)&Bh[col][p0 + 8];
                bl[ks][0] = *(const uint32_t*)&Bl[col][p0];
                bl[ks][1] = *(const uint32_t*)&Bl[col][p0 + 8];
            }
            #pragma unroll
            for (int mf = 0; mf < 2; mf++) {
                #pragma unroll
                for (int ks = 0; ks < 2; ks++) {
                    mma16816(c[mf][nf], ah[mf][ks][0], ah[mf][ks][1],
                             ah[mf][ks][2], ah[mf][ks][3], bh[ks][0], bh[ks][1]);
                    mma16816(c[mf][nf], al[mf][ks][0], al[mf][ks][1],
                             al[mf][ks][2], al[mf][ks][3], bh[ks][0], bh[ks][1]);
                    mma16816(c[mf][nf], ah[mf][ks][0], ah[mf][ks][1],
                             ah[mf][ks][2], ah[mf][ks][3], bl[ks][0], bl[ks][1]);
                }
            }
        }
        __syncthreads();
    }

    // epilogue: + bias, split to bf16 hi/lo, head-split store
    #pragma unroll
    for (int mf = 0; mf < 2; mf++) {
        int rr[2] = { m0 + wm * 32 + mf * 16 + g, m0 + wm * 32 + mf * 16 + g + 8 };
        #pragma unroll
        for (int nf = 0; nf < 4; nf++) {
            int n = n0 + wn * 32 + nf * 8 + 2 * tig;
            int h = n >> 5, p = n & 31;
            float b0 = bias[n], b1 = bias[n + 1];
            #pragma unroll
            for (int half = 0; half < 2; half++) {
                int m = rr[half];
                int bb = m / S_LEN, s = m % S_LEN;
                float v0 = c[mf][nf][2 * half] + b0;
                float v1 = c[mf][nf][2 * half + 1] + b1;
                __nv_bfloat16 h0, l0, h1, l1;
                split2(v0, h0, l0); split2(v1, h1, l1);
                if (z == 2) {
                    // V: transposed [B,H,P,S]
                    size_t tb = ((size_t)(bb * H_NUM + h) * P_DIM + p) * S_LEN + s;
                    g_vth[tb] = h0; g_vth[tb + S_LEN] = h1;
                    g_vtl[tb] = l0; g_vtl[tb + S_LEN] = l1;
                } else {
                    size_t idx = ((size_t)(bb * H_NUM + h) * S_LEN + s) * P_DIM + p;
                    uint32_t ph = ((uint32_t)__bfloat16_as_ushort(h1) << 16) |
                                  __bfloat16_as_ushort(h0);
                    uint32_t pl = ((uint32_t)__bfloat16_as_ushort(l1) << 16) |
                                  __bfloat16_as_ushort(l0);
                    if (z == 0) { *(uint32_t*)&g_qh[idx] = ph; *(uint32_t*)&g_ql[idx] = pl; }
                    else        { *(uint32_t*)&g_kh[idx] = ph; *(uint32_t*)&g_kl[idx] = pl; }
                }
            }
        }
    }
}

// ---------------------------------------------------------------------------
// Kernel 2: flash attention, pre-split operands + cp.async double buffering.
// grid = (14, 16), block = 256 (8 warps, warp = 16 q rows).
// ---------------------------------------------------------------------------
__global__ __launch_bounds__(256, 2) void attn_mma_kernel()
{
    __shared__ __nv_bfloat16 Kh[2][KN][40], Kl[2][KN][40];
    __shared__ __nv_bfloat16 Vth[2][P_DIM][72], Vtl[2][P_DIM][72];

    const int tid  = threadIdx.x;
    const int warp = tid >> 5, lane = tid & 31;
    const int g    = lane >> 2, tig = lane & 3;
    const int woff = warp * 16;
    const int bh   = blockIdx.y;
    const int q0   = blockIdx.x * QT;

    const size_t bhSP = (size_t)bh * S_LEN * P_DIM;
    const size_t bhPS = (size_t)bh * P_DIM * S_LEN;

    // cp.async tile loader: 4 x 16B per thread
    const int kr = tid >> 2, kc = (tid & 3) * 8;       // K: 64 rows x 4 chunks
    const int vp = tid >> 3, vc = (tid & 7) * 8;       // Vt: 32 rows x 8 chunks
    uint32_t sKh[2], sKl[2], sVh[2], sVl[2];
    #pragma unroll
    for (int b = 0; b < 2; b++) {
        sKh[b] = smem_u32(&Kh[b][kr][kc]);
        sKl[b] = smem_u32(&Kl[b][kr][kc]);
        sVh[b] = smem_u32(&Vth[b][vp][vc]);
        sVl[b] = smem_u32(&Vtl[b][vp][vc]);
    }

    #define LOAD_TILE(kt, b) do {                                             \
        int _k0 = (kt) * KN;                                                  \
        cp16(sKh[b], &g_kh[bhSP + (size_t)(_k0 + kr) * P_DIM + kc]);          \
        cp16(sKl[b], &g_kl[bhSP + (size_t)(_k0 + kr) * P_DIM + kc]);          \
        cp16(sVh[b], &g_vth[bhPS + (size_t)vp * S_LEN + _k0 + vc]);          \
        cp16(sVl[b], &g_vtl[bhPS + (size_t)vp * S_LEN + _k0 + vc]);          \
    } while (0)

    LOAD_TILE(0, 0);
    CP_COMMIT();

    // Q fragments straight from global (rows may exceed S_LEN -> zeros)
    const int r0g = q0 + woff + g;
    const bool v0 = r0g < S_LEN, v1 = (r0g + 8) < S_LEN;
    const size_t qb0 = bhSP + (size_t)r0g * P_DIM;
    const size_t qb1 = qb0 + 8 * P_DIM;
    uint32_t qh[2][4], ql[2][4];
    #pragma unroll
    for (int ks = 0; ks < 2; ks++) {
        int p0 = ks * 16 + 2 * tig;
        qh[ks][0] = v0 ? *(const uint32_t*)&g_qh[qb0 + p0] : 0u;
        qh[ks][1] = v1 ? *(const uint32_t*)&g_qh[qb1 + p0] : 0u;
        qh[ks][2] = v0 ? *(const uint32_t*)&g_qh[qb0 + p0 + 8] : 0u;
        qh[ks][3] = v1 ? *(const uint32_t*)&g_qh[qb1 + p0 + 8] : 0u;
        ql[ks][0] = v0 ? *(const uint32_t*)&g_ql[qb0 + p0] : 0u;
        ql[ks][1] = v1 ? *(const uint32_t*)&g_ql[qb1 + p0] : 0u;
        ql[ks][2] = v0 ? *(const uint32_t*)&g_ql[qb0 + p0 + 8] : 0u;
        ql[ks][3] = v1 ? *(const uint32_t*)&g_ql[qb1 + p0 + 8] : 0u;
    }

    float o[4][4] = {};
    float l0 = 0.f, l1 = 0.f;

    for (int kt = 0; kt < NKT; kt++) {
        const int buf = kt & 1;
        if (kt + 1 < NKT) {
            LOAD_TILE(kt + 1, buf ^ 1);
            CP_COMMIT();
            CP_WAIT(1);
        } else {
            CP_WAIT(0);
        }
        __syncthreads();

        // scores (16x64 per warp), exp, pack P fragments
        uint32_t phi01[8], phi23[8], plo01[8], plo23[8];
        #pragma unroll
        for (int nt = 0; nt < 8; nt++) {
            float c[4] = {0.f, 0.f, 0.f, 0.f};
            const int key = 8 * nt + g;
            #pragma unroll
            for (int ks = 0; ks < 2; ks++) {
                int p0 = ks * 16 + 2 * tig;
                uint32_t b0h = *(const uint32_t*)&Kh[buf][key][p0];
                uint32_t b1h = *(const uint32_t*)&Kh[buf][key][p0 + 8];
                uint32_t b0l = *(const uint32_t*)&Kl[buf][key][p0];
                uint32_t b1l = *(const uint32_t*)&Kl[buf][key][p0 + 8];
                mma16816(c, qh[ks][0], qh[ks][1], qh[ks][2], qh[ks][3], b0h, b1h);
                mma16816(c, ql[ks][0], ql[ks][1], ql[ks][2], ql[ks][3], b0h, b1h);
                mma16816(c, qh[ks][0], qh[ks][1], qh[ks][2], qh[ks][3], b0l, b1l);
            }
            float e0 = __expf(c[0]);
            float e1 = __expf(c[1]);
            float e2 = __expf(c[2]);
            float e3 = __expf(c[3]);
            l0 += e0 + e1;
            l1 += e2 + e3;
            __nv_bfloat16 h0 = __float2bfloat16(e0), h1 = __float2bfloat16(e1);
            __nv_bfloat16 h2 = __float2bfloat16(e2), h3 = __float2bfloat16(e3);
            phi01[nt] = ((uint32_t)__bfloat16_as_ushort(h1) << 16) |
                        (uint32_t)__bfloat16_as_ushort(h0);
            phi23[nt] = ((uint32_t)__bfloat16_as_ushort(h3) << 16) |
                        (uint32_t)__bfloat16_as_ushort(h2);
            plo01[nt] = pack_bf16(e0 - __bfloat162float(h0), e1 - __bfloat162float(h1));
            plo23[nt] = pack_bf16(e2 - __bfloat162float(h2), e3 - __bfloat162float(h3));
        }

        // PV: O(16x32) += P(16x64) @ V(64x32)
        #pragma unroll
        for (int n = 0; n < 4; n++) {
            const int prow = 8 * n + g;
            #pragma unroll
            for (int ks = 0; ks < 4; ks++) {
                int kb = ks * 16 + 2 * tig;
                uint32_t b0h = *(const uint32_t*)&Vth[buf][prow][kb];
                uint32_t b1h = *(const uint32_t*)&Vth[buf][prow][kb + 8];
                uint32_t b0l = *(const uint32_t*)&Vtl[buf][prow][kb];
                uint32_t b1l = *(const uint32_t*)&Vtl[buf][prow][kb + 8];
                uint32_t a0 = phi01[2 * ks], a1 = phi23[2 * ks];
                uint32_t a2 = phi01[2 * ks + 1], a3 = phi23[2 * ks + 1];
                mma16816(o[n], a0, a1, a2, a3, b0h, b1h);
                mma16816(o[n], a0, a1, a2, a3, b0l, b1l);
                mma16816(o[n], plo01[2 * ks], plo23[2 * ks],
                               plo01[2 * ks + 1], plo23[2 * ks + 1], b0h, b1h);
            }
        }
        __syncthreads();
    }

    l0 += __shfl_xor_sync(0xffffffffu, l0, 1);
    l0 += __shfl_xor_sync(0xffffffffu, l0, 2);
    l1 += __shfl_xor_sync(0xffffffffu, l1, 1);
    l1 += __shfl_xor_sync(0xffffffffu, l1, 2);
    const float inv0 = 1.0f / l0;
    const float inv1 = 1.0f / l1;

    // store O split-bf16 into g_oh/g_ol [B*S, E]
    const int b = bh >> 3, h = bh & 7;
    const int r1g = r0g + 8;
    #pragma unroll
    for (int n = 0; n < 4; n++) {
        int p = 8 * n + 2 * tig;
        if (v0) {
            float w0 = o[n][0] * inv0, w1 = o[n][1] * inv0;
            __nv_bfloat16 h0, lb0, h1, lb1;
            split2(w0, h0, lb0); split2(w1, h1, lb1);
            size_t idx = ((size_t)b * S_LEN + r0g) * E_DIM + h * P_DIM + p;
            *(uint32_t*)&g_oh[idx] = ((uint32_t)__bfloat16_as_ushort(h1) << 16) |
                                     __bfloat16_as_ushort(h0);
            *(uint32_t*)&g_ol[idx] = ((uint32_t)__bfloat16_as_ushort(lb1) << 16) |
                                     __bfloat16_as_ushort(lb0);
        }
        if (v1) {
            float w0 = o[n][2] * inv1, w1 = o[n][3] * inv1;
            __nv_bfloat16 h0, lb0, h1, lb1;
            split2(w0, h0, lb0); split2(w1, h1, lb1);
            size_t idx = ((size_t)b * S_LEN + r1g) * E_DIM + h * P_DIM + p;
            *(uint32_t*)&g_oh[idx] = ((uint32_t)__bfloat16_as_ushort(h1) << 16) |
                                     __bfloat16_as_ushort(h0);
            *(uint32_t*)&g_ol[idx] = ((uint32_t)__bfloat16_as_ushort(lb1) << 16) |
                                     __bfloat16_as_ushort(lb0);
        }
    }
}

// ---------------------------------------------------------------------------
// Kernel 3: output projection on tensor cores. grid (27, 4), block 256.
// ---------------------------------------------------------------------------
__global__ __launch_bounds__(256) void out_mma_kernel(
    const float* __restrict__ bo, float* __restrict__ out)
{
    __shared__ __nv_bfloat16 Ah[128][40], Al[128][40];
    __shared__ __nv_bfloat16 Bh[64][40], Bl[64][40];

    const int tid = threadIdx.x;
    const int warp = tid >> 5, lane = tid & 31;
    const int g = lane >> 2, tig = lane & 3;
    const int wm = warp >> 1, wn = warp & 1;
    const int m0 = blockIdx.x * 128;
    const int n0 = blockIdx.y * 64;

    const __nv_bfloat16* wth = g_wth + (size_t)3 * E_DIM * E_DIM;
    const __nv_bfloat16* wtl = g_wtl + (size_t)3 * E_DIM * E_DIM;

    float c[2][4][4] = {};

    for (int k0 = 0; k0 < E_DIM; k0 += 32) {
        #pragma unroll
        for (int i = 0; i < 2; i++) {
            int e = tid + i * 256;
            int r = e >> 2, cc = (e & 3) * 8;
            *(uint4*)&Ah[r][cc] = *(const uint4*)&g_oh[(size_t)(m0 + r) * E_DIM + k0 + cc];
            *(uint4*)&Al[r][cc] = *(const uint4*)&g_ol[(size_t)(m0 + r) * E_DIM + k0 + cc];
        }
        {
            int r = tid >> 2, cc = (tid & 3) * 8;
            *(uint4*)&Bh[r][cc] = *(const uint4*)&wth[(size_t)(n0 + r) * E_DIM + k0 + cc];
            *(uint4*)&Bl[r][cc] = *(const uint4*)&wtl[(size_t)(n0 + r) * E_DIM + k0 + cc];
        }
        __syncthreads();

        uint32_t ah[2][2][4], al[2][2][4];
        #pragma unroll
        for (int mf = 0; mf < 2; mf++) {
            int r = wm * 32 + mf * 16 + g;
            #pragma unroll
            for (int ks = 0; ks < 2; ks++) {
                int p0 = ks * 16 + 2 * tig;
                ah[mf][ks][0] = *(const uint32_t*)&Ah[r][p0];
                ah[mf][ks][1] = *(const uint32_t*)&Ah[r + 8][p0];
                ah[mf][ks][2] = *(const uint32_t*)&Ah[r][p0 + 8];
                ah[mf][ks][3] = *(const uint32_t*)&Ah[r + 8][p0 + 8];
                al[mf][ks][0] = *(const uint32_t*)&Al[r][p0];
                al[mf][ks][1] = *(const uint32_t*)&Al[r + 8][p0];
                al[mf][ks][2] = *(const uint32_t*)&Al[r][p0 + 8];
                al[mf][ks][3] = *(const uint32_t*)&Al[r + 8][p0 + 8];
            }
        }
        #pragma unroll
        for (int nf = 0; nf < 4; nf++) {
            int col = wn * 32 + nf * 8 + g;
            uint32_t bh[2][2], bl[2][2];
            #pragma unroll
            for (int ks = 0; ks < 2; ks++) {
                int p0 = ks * 16 + 2 * tig;
                bh[ks][0] = *(const uint32_t*)&Bh[col][p0];
                bh[ks][1] = *(const uint32_t*)&Bh[col][p0 + 8];
                bl[ks][0] = *(const uint32_t*)&Bl[col][p0];
                bl[ks][1] = *(const uint32_t*)&Bl[col][p0 + 8];
            }
            #pragma unroll
            for (int mf = 0; mf < 2; mf++) {
                #pragma unroll
                for (int ks = 0; ks < 2; ks++) {
                    mma16816(c[mf][nf], ah[mf][ks][0], ah[mf][ks][1],
                             ah[mf][ks][2], ah[mf][ks][3], bh[ks][0], bh[ks][1]);
                    mma16816(c[mf][nf], al[mf][ks][0], al[mf][ks][1],
                             al[mf][ks][2], al[mf][ks][3], bh[ks][0], bh[ks][1]);
                    mma16816(c[mf][nf], ah[mf][ks][0], ah[mf][ks][1],
                             ah[mf][ks][2], ah[mf][ks][3], bl[ks][0], bl[ks][1]);
                }
            }
        }
        __syncthreads();
    }

    #pragma unroll
    for (int mf = 0; mf < 2; mf++) {
        int r0 = m0 + wm * 32 + mf * 16 + g;
        int r1 = r0 + 8;
        #pragma unroll
        for (int nf = 0; nf < 4; nf++) {
            int n = n0 + wn * 32 + nf * 8 + 2 * tig;
            float b0 = bo[n], b1 = bo[n + 1];
            *(float2*)&out[(size_t)r0 * E_DIM + n] =
                make_float2(c[mf][nf][0] + b0, c[mf][nf][1] + b1);
            *(float2*)&out[(size_t)r1 * E_DIM + n] =
                make_float2(c[mf][nf][2] + b0, c[mf][nf][3] + b1);
        }
    }
}

extern "C" void kernel_launch(void* const* d_in, const int* in_sizes, int n_in,
                              void* d_out, int out_size)
{
    const float* x  = (const float*)d_in[0];
    const float* bq = (const float*)d_in[2];
    const float* bk = (const float*)d_in[4];
    const float* bv = (const float*)d_in[6];
    const float* bo = (const float*)d_in[8];
    float* out = (float*)d_out;

    prep_x_kernel<<<M_ROWS * E_DIM / 1024, 256>>>(x);
    prep_w_kernel<<<dim3(8, 8, 4), 256>>>(
        (const float*)d_in[1], (const float*)d_in[3],
        (const float*)d_in[5], (const float*)d_in[7]);
    qkv_mma_kernel<<<dim3(27, 4, 3), 256>>>(bq, bk, bv);
    attn_mma_kernel<<<dim3(14, 16), 256>>>();
    out_mma_kernel<<<dim3(27, 4), 256>>>(bo, out);
}

// round 10
// speedup vs baseline: 2.5760x; 1.1232x over previous
#include <cuda_runtime.h>
#include <cuda_bf16.h>
#include <cstdint>

#define S_LEN 1728
#define B_SZ 2
#define E_DIM 256
#define H_NUM 8
#define P_DIM 32
#define M_ROWS (B_SZ * S_LEN)   // 3456

#define QT 128                  // q rows per block (attn)
#define KN 64                   // keys per tile (attn)
#define NKT (S_LEN / KN)        // 27

#define LOG2E 1.44269504088896340736f

// split-bf16 scratch (no allocations allowed)
__device__ __align__(16) __nv_bfloat16 g_qh[B_SZ * H_NUM * S_LEN * P_DIM]; // [B,H,S,P]
__device__ __align__(16) __nv_bfloat16 g_ql[B_SZ * H_NUM * S_LEN * P_DIM];
__device__ __align__(16) __nv_bfloat16 g_kh[B_SZ * H_NUM * S_LEN * P_DIM];
__device__ __align__(16) __nv_bfloat16 g_kl[B_SZ * H_NUM * S_LEN * P_DIM];
__device__ __align__(16) __nv_bfloat16 g_vth[B_SZ * H_NUM * P_DIM * S_LEN]; // [B,H,P,S]
__device__ __align__(16) __nv_bfloat16 g_vtl[B_SZ * H_NUM * P_DIM * S_LEN];
__device__ __align__(16) __nv_bfloat16 g_xh[M_ROWS * E_DIM];
__device__ __align__(16) __nv_bfloat16 g_xl[M_ROWS * E_DIM];
__device__ __align__(16) __nv_bfloat16 g_wth[4 * E_DIM * E_DIM];  // Wt[n][k], z=q,k,v,o
__device__ __align__(16) __nv_bfloat16 g_wtl[4 * E_DIM * E_DIM];
__device__ __align__(16) __nv_bfloat16 g_oh[M_ROWS * E_DIM];      // attn out hi
__device__ __align__(16) __nv_bfloat16 g_ol[M_ROWS * E_DIM];      // attn out lo

// ---------------------------------------------------------------------------
// helpers
// ---------------------------------------------------------------------------
__device__ __forceinline__ void mma16816(float c[4],
    uint32_t a0, uint32_t a1, uint32_t a2, uint32_t a3,
    uint32_t b0, uint32_t b1)
{
    asm volatile(
        "mma.sync.aligned.m16n8k16.row.col.f32.bf16.bf16.f32 "
        "{%0,%1,%2,%3}, {%4,%5,%6,%7}, {%8,%9}, {%0,%1,%2,%3};"
        : "+f"(c[0]), "+f"(c[1]), "+f"(c[2]), "+f"(c[3])
        : "r"(a0), "r"(a1), "r"(a2), "r"(a3), "r"(b0), "r"(b1));
}

__device__ __forceinline__ void ldsm_x4(uint32_t r[4], uint32_t addr) {
    asm volatile("ldmatrix.sync.aligned.m8n8.x4.shared.b16 {%0,%1,%2,%3}, [%4];"
                 : "=r"(r[0]), "=r"(r[1]), "=r"(r[2]), "=r"(r[3]) : "r"(addr));
}

__device__ __forceinline__ uint32_t smem_u32(const void* p) {
    uint32_t a;
    asm("{ .reg .u64 t; cvta.to.shared.u64 t, %1; cvt.u32.u64 %0, t; }"
        : "=r"(a) : "l"(p));
    return a;
}
__device__ __forceinline__ void cp16(uint32_t saddr, const void* g) {
    asm volatile("cp.async.cg.shared.global [%0], [%1], 16;"
                 :: "r"(saddr), "l"(g) : "memory");
}
#define CP_COMMIT() asm volatile("cp.async.commit_group;" ::: "memory")
#define CP_WAIT(N)  asm volatile("cp.async.wait_group %0;" :: "n"(N) : "memory")

__device__ __forceinline__ float ex2f(float x) {
    float y;
    asm("ex2.approx.ftz.f32 %0, %1;" : "=f"(y) : "f"(x));
    return y;
}
// pack (lo, hi) floats into bf16x2 register
__device__ __forceinline__ uint32_t pack_bf16x2(float lo, float hi) {
    uint32_t r;
    asm("cvt.rn.bf16x2.f32 %0, %1, %2;" : "=r"(r) : "f"(hi), "f"(lo));
    return r;
}
__device__ __forceinline__ void split2(float v, __nv_bfloat16& h, __nv_bfloat16& l) {
    h = __float2bfloat16(v);
    l = __float2bfloat16(v - __bfloat162float(h));
}

// ---------------------------------------------------------------------------
// Prep 1: split x -> g_xh/g_xl. grid 864, block 256.
// ---------------------------------------------------------------------------
__global__ __launch_bounds__(256) void prep_x_kernel(const float* __restrict__ x)
{
    int i = (blockIdx.x * 256 + threadIdx.x) * 4;
    float4 v = *(const float4*)&x[i];
    uint2 hi, lo;
    hi.x = pack_bf16x2(v.x, v.y);
    hi.y = pack_bf16x2(v.z, v.w);
    lo.x = pack_bf16x2(v.x - __uint_as_float(hi.x << 16),
                       v.y - __uint_as_float(hi.x & 0xffff0000u));
    lo.y = pack_bf16x2(v.z - __uint_as_float(hi.y << 16),
                       v.w - __uint_as_float(hi.y & 0xffff0000u));
    *(uint2*)&g_xh[i] = hi;
    *(uint2*)&g_xl[i] = lo;
}

// ---------------------------------------------------------------------------
// Prep 2: transpose + split weights -> g_wth/g_wtl. grid (8, 8, 4), block 256.
// ---------------------------------------------------------------------------
__global__ __launch_bounds__(256) void prep_w_kernel(
    const float* __restrict__ Wq, const float* __restrict__ Wk,
    const float* __restrict__ Wv, const float* __restrict__ Wo)
{
    __shared__ float s[32][33];
    const int z = blockIdx.z;
    const float* W = (z == 0) ? Wq : (z == 1) ? Wk : (z == 2) ? Wv : Wo;
    const int k0 = blockIdx.x * 32, n0 = blockIdx.y * 32;
    const int c = threadIdx.x & 31, r0 = threadIdx.x >> 5;
    #pragma unroll
    for (int i = 0; i < 4; i++) {
        int r = r0 + i * 8;
        s[r][c] = W[(k0 + r) * E_DIM + n0 + c];
    }
    __syncthreads();
    #pragma unroll
    for (int i = 0; i < 4; i++) {
        int r = r0 + i * 8;
        float v = s[c][r];
        __nv_bfloat16 h, l; split2(v, h, l);
        size_t idx = (size_t)z * E_DIM * E_DIM + (size_t)(n0 + r) * E_DIM + k0 + c;
        g_wth[idx] = h;
        g_wtl[idx] = l;
    }
}

// ---------------------------------------------------------------------------
// Kernel 1: QKV projection, bf16-split 3-MMA. grid (27, 4, 3), block 256.
// Q outputs are prescaled by log2(e) so attention can use bare ex2.
// V stored transposed [B,H,P,S].
// ---------------------------------------------------------------------------
__global__ __launch_bounds__(256) void qkv_mma_kernel(
    const float* __restrict__ bq, const float* __restrict__ bk,
    const float* __restrict__ bv)
{
    __shared__ __nv_bfloat16 Ah[128][40], Al[128][40];
    __shared__ __nv_bfloat16 Bh[64][40], Bl[64][40];

    const int tid = threadIdx.x;
    const int warp = tid >> 5, lane = tid & 31;
    const int g = lane >> 2, tig = lane & 3;
    const int wm = warp >> 1, wn = warp & 1;
    const int m0 = blockIdx.x * 128;
    const int n0 = blockIdx.y * 64;
    const int z  = blockIdx.z;

    const __nv_bfloat16* wth = g_wth + (size_t)z * E_DIM * E_DIM;
    const __nv_bfloat16* wtl = g_wtl + (size_t)z * E_DIM * E_DIM;
    const float* bias = (z == 0) ? bq : (z == 1) ? bk : bv;
    const float outscale = (z == 0) ? LOG2E : 1.0f;

    float c[2][4][4] = {};

    for (int k0 = 0; k0 < E_DIM; k0 += 32) {
        #pragma unroll
        for (int i = 0; i < 2; i++) {
            int e = tid + i * 256;
            int r = e >> 2, cc = (e & 3) * 8;
            *(uint4*)&Ah[r][cc] = *(const uint4*)&g_xh[(size_t)(m0 + r) * E_DIM + k0 + cc];
            *(uint4*)&Al[r][cc] = *(const uint4*)&g_xl[(size_t)(m0 + r) * E_DIM + k0 + cc];
        }
        {
            int r = tid >> 2, cc = (tid & 3) * 8;
            *(uint4*)&Bh[r][cc] = *(const uint4*)&wth[(size_t)(n0 + r) * E_DIM + k0 + cc];
            *(uint4*)&Bl[r][cc] = *(const uint4*)&wtl[(size_t)(n0 + r) * E_DIM + k0 + cc];
        }
        __syncthreads();

        uint32_t ah[2][2][4], al[2][2][4];
        #pragma unroll
        for (int mf = 0; mf < 2; mf++) {
            int r = wm * 32 + mf * 16 + g;
            #pragma unroll
            for (int ks = 0; ks < 2; ks++) {
                int p0 = ks * 16 + 2 * tig;
                ah[mf][ks][0] = *(const uint32_t*)&Ah[r][p0];
                ah[mf][ks][1] = *(const uint32_t*)&Ah[r + 8][p0];
                ah[mf][ks][2] = *(const uint32_t*)&Ah[r][p0 + 8];
                ah[mf][ks][3] = *(const uint32_t*)&Ah[r + 8][p0 + 8];
                al[mf][ks][0] = *(const uint32_t*)&Al[r][p0];
                al[mf][ks][1] = *(const uint32_t*)&Al[r + 8][p0];
                al[mf][ks][2] = *(const uint32_t*)&Al[r][p0 + 8];
                al[mf][ks][3] = *(const uint32_t*)&Al[r + 8][p0 + 8];
            }
        }
        #pragma unroll
        for (int nf = 0; nf < 4; nf++) {
            int col = wn * 32 + nf * 8 + g;
            uint32_t bh[2][2], bl[2][2];
            #pragma unroll
            for (int ks = 0; ks < 2; ks++) {
                int p0 = ks * 16 + 2 * tig;
                bh[ks][0] = *(const uint32_t*)&Bh[col][p0];
                bh[ks][1] = *(const uint32_t*)&Bh[col][p0 + 8];
                bl[ks][0] = *(const uint32_t*)&Bl[col][p0];
                bl[ks][1] = *(const uint32_t*)&Bl[col][p0 + 8];
            }
            #pragma unroll
            for (int mf = 0; mf < 2; mf++) {
                #pragma unroll
                for (int ks = 0; ks < 2; ks++) {
                    mma16816(c[mf][nf], ah[mf][ks][0], ah[mf][ks][1],
                             ah[mf][ks][2], ah[mf][ks][3], bh[ks][0], bh[ks][1]);
                    mma16816(c[mf][nf], al[mf][ks][0], al[mf][ks][1],
                             al[mf][ks][2], al[mf][ks][3], bh[ks][0], bh[ks][1]);
                    mma16816(c[mf][nf], ah[mf][ks][0], ah[mf][ks][1],
                             ah[mf][ks][2], ah[mf][ks][3], bl[ks][0], bl[ks][1]);
                }
            }
        }
        __syncthreads();
    }

    // epilogue: + bias, optional log2e scale, split to bf16 hi/lo, store
    #pragma unroll
    for (int mf = 0; mf < 2; mf++) {
        int rr[2] = { m0 + wm * 32 + mf * 16 + g, m0 + wm * 32 + mf * 16 + g + 8 };
        #pragma unroll
        for (int nf = 0; nf < 4; nf++) {
            int n = n0 + wn * 32 + nf * 8 + 2 * tig;
            int h = n >> 5, p = n & 31;
            float b0 = bias[n], b1 = bias[n + 1];
            #pragma unroll
            for (int half = 0; half < 2; half++) {
                int m = rr[half];
                int bb = m / S_LEN, s = m % S_LEN;
                float v0 = (c[mf][nf][2 * half] + b0) * outscale;
                float v1 = (c[mf][nf][2 * half + 1] + b1) * outscale;
                __nv_bfloat16 h0, l0, h1, l1;
                split2(v0, h0, l0); split2(v1, h1, l1);
                if (z == 2) {
                    size_t tb = ((size_t)(bb * H_NUM + h) * P_DIM + p) * S_LEN + s;
                    g_vth[tb] = h0; g_vth[tb + S_LEN] = h1;
                    g_vtl[tb] = l0; g_vtl[tb + S_LEN] = l1;
                } else {
                    size_t idx = ((size_t)(bb * H_NUM + h) * S_LEN + s) * P_DIM + p;
                    uint32_t ph = ((uint32_t)__bfloat16_as_ushort(h1) << 16) |
                                  __bfloat16_as_ushort(h0);
                    uint32_t pl = ((uint32_t)__bfloat16_as_ushort(l1) << 16) |
                                  __bfloat16_as_ushort(l0);
                    if (z == 0) { *(uint32_t*)&g_qh[idx] = ph; *(uint32_t*)&g_ql[idx] = pl; }
                    else        { *(uint32_t*)&g_kh[idx] = ph; *(uint32_t*)&g_kl[idx] = pl; }
                }
            }
        }
    }
}

// ---------------------------------------------------------------------------
// Kernel 2: flash attention; pre-split operands, cp.async double buffering,
// ldmatrix B-fragments, log2-domain softmax (Q prescaled by log2e).
// grid = (14, 16), block = 256 (8 warps, warp = 16 q rows).
// ---------------------------------------------------------------------------
__global__ __launch_bounds__(256, 2) void attn_mma_kernel()
{
    __shared__ __nv_bfloat16 Kh[2][KN][40], Kl[2][KN][40];
    __shared__ __nv_bfloat16 Vth[2][P_DIM][72], Vtl[2][P_DIM][72];

    const int tid  = threadIdx.x;
    const int warp = tid >> 5, lane = tid & 31;
    const int g    = lane >> 2, tig = lane & 3;
    const int l8   = lane & 7, lq = lane >> 3;
    const int woff = warp * 16;
    const int bh   = blockIdx.y;
    const int q0   = blockIdx.x * QT;

    const size_t bhSP = (size_t)bh * S_LEN * P_DIM;
    const size_t bhPS = (size_t)bh * P_DIM * S_LEN;

    // cp.async tile loader: 4 x 16B per thread
    const int kr = tid >> 2, kc = (tid & 3) * 8;       // K: 64 rows x 4 chunks
    const int vp = tid >> 3, vc = (tid & 7) * 8;       // Vt: 32 rows x 8 chunks
    uint32_t sKh[2], sKl[2], sVh[2], sVl[2];
    // ldmatrix per-lane base addresses (rows l8, col block 8*lq)
    uint32_t aKh[2], aKl[2], aVh[2], aVl[2];
    #pragma unroll
    for (int b = 0; b < 2; b++) {
        sKh[b] = smem_u32(&Kh[b][kr][kc]);
        sKl[b] = smem_u32(&Kl[b][kr][kc]);
        sVh[b] = smem_u32(&Vth[b][vp][vc]);
        sVl[b] = smem_u32(&Vtl[b][vp][vc]);
        aKh[b] = smem_u32(&Kh[b][l8][8 * lq]);
        aKl[b] = smem_u32(&Kl[b][l8][8 * lq]);
        aVh[b] = smem_u32(&Vth[b][l8][8 * lq]);
        aVl[b] = smem_u32(&Vtl[b][l8][8 * lq]);
    }

    #define LOAD_TILE(kt, b) do {                                             \
        int _k0 = (kt) * KN;                                                  \
        cp16(sKh[b], &g_kh[bhSP + (size_t)(_k0 + kr) * P_DIM + kc]);          \
        cp16(sKl[b], &g_kl[bhSP + (size_t)(_k0 + kr) * P_DIM + kc]);          \
        cp16(sVh[b], &g_vth[bhPS + (size_t)vp * S_LEN + _k0 + vc]);          \
        cp16(sVl[b], &g_vtl[bhPS + (size_t)vp * S_LEN + _k0 + vc]);          \
    } while (0)

    LOAD_TILE(0, 0);
    CP_COMMIT();

    // Q fragments straight from global (rows may exceed S_LEN -> zeros)
    const int r0g = q0 + woff + g;
    const bool v0 = r0g < S_LEN, v1 = (r0g + 8) < S_LEN;
    const size_t qb0 = bhSP + (size_t)r0g * P_DIM;
    const size_t qb1 = qb0 + 8 * P_DIM;
    uint32_t qh[2][4], ql[2][4];
    #pragma unroll
    for (int ks = 0; ks < 2; ks++) {
        int p0 = ks * 16 + 2 * tig;
        qh[ks][0] = v0 ? *(const uint32_t*)&g_qh[qb0 + p0] : 0u;
        qh[ks][1] = v1 ? *(const uint32_t*)&g_qh[qb1 + p0] : 0u;
        qh[ks][2] = v0 ? *(const uint32_t*)&g_qh[qb0 + p0 + 8] : 0u;
        qh[ks][3] = v1 ? *(const uint32_t*)&g_qh[qb1 + p0 + 8] : 0u;
        ql[ks][0] = v0 ? *(const uint32_t*)&g_ql[qb0 + p0] : 0u;
        ql[ks][1] = v1 ? *(const uint32_t*)&g_ql[qb1 + p0] : 0u;
        ql[ks][2] = v0 ? *(const uint32_t*)&g_ql[qb0 + p0 + 8] : 0u;
        ql[ks][3] = v1 ? *(const uint32_t*)&g_ql[qb1 + p0 + 8] : 0u;
    }

    float o[4][4] = {};
    float l0 = 0.f, l1 = 0.f;

    for (int kt = 0; kt < NKT; kt++) {
        const int buf = kt & 1;
        if (kt + 1 < NKT) {
            LOAD_TILE(kt + 1, buf ^ 1);
            CP_COMMIT();
            CP_WAIT(1);
        } else {
            CP_WAIT(0);
        }
        __syncthreads();

        // scores (16x64 per warp): ldmatrix x4 gives b-frags for both ksteps
        uint32_t phi01[8], phi23[8], plo01[8], plo23[8];
        #pragma unroll
        for (int nt = 0; nt < 8; nt++) {
            uint32_t kh4[4], kl4[4];
            ldsm_x4(kh4, aKh[buf] + nt * (8 * 40 * 2));
            ldsm_x4(kl4, aKl[buf] + nt * (8 * 40 * 2));
            float c[4] = {0.f, 0.f, 0.f, 0.f};
            mma16816(c, qh[0][0], qh[0][1], qh[0][2], qh[0][3], kh4[0], kh4[1]);
            mma16816(c, ql[0][0], ql[0][1], ql[0][2], ql[0][3], kh4[0], kh4[1]);
            mma16816(c, qh[0][0], qh[0][1], qh[0][2], qh[0][3], kl4[0], kl4[1]);
            mma16816(c, qh[1][0], qh[1][1], qh[1][2], qh[1][3], kh4[2], kh4[3]);
            mma16816(c, ql[1][0], ql[1][1], ql[1][2], ql[1][3], kh4[2], kh4[3]);
            mma16816(c, qh[1][0], qh[1][1], qh[1][2], qh[1][3], kl4[2], kl4[3]);

            // scores are log2-domain: p = 2^s
            float e0 = ex2f(c[0]);
            float e1 = ex2f(c[1]);
            float e2 = ex2f(c[2]);
            float e3 = ex2f(c[3]);
            l0 += e0 + e1;
            l1 += e2 + e3;
            uint32_t ph01 = pack_bf16x2(e0, e1);
            uint32_t ph23 = pack_bf16x2(e2, e3);
            phi01[nt] = ph01;
            phi23[nt] = ph23;
            plo01[nt] = pack_bf16x2(e0 - __uint_as_float(ph01 << 16),
                                    e1 - __uint_as_float(ph01 & 0xffff0000u));
            plo23[nt] = pack_bf16x2(e2 - __uint_as_float(ph23 << 16),
                                    e3 - __uint_as_float(ph23 & 0xffff0000u));
        }

        // PV: O(16x32) += P(16x64) @ V(64x32); ldmatrix covers 2 ksteps per x4
        #pragma unroll
        for (int n = 0; n < 4; n++) {
            uint32_t vhA[4], vhB[4], vlA[4], vlB[4];
            uint32_t base = n * (8 * 72 * 2);
            ldsm_x4(vhA, aVh[buf] + base);
            ldsm_x4(vhB, aVh[buf] + base + 64);
            ldsm_x4(vlA, aVl[buf] + base);
            ldsm_x4(vlB, aVl[buf] + base + 64);
            #pragma unroll
            for (int ks = 0; ks < 4; ks++) {
                uint32_t b0h = (ks < 2 ? vhA : vhB)[2 * (ks & 1)];
                uint32_t b1h = (ks < 2 ? vhA : vhB)[2 * (ks & 1) + 1];
                uint32_t b0l = (ks < 2 ? vlA : vlB)[2 * (ks & 1)];
                uint32_t b1l = (ks < 2 ? vlA : vlB)[2 * (ks & 1) + 1];
                uint32_t a0 = phi01[2 * ks], a1 = phi23[2 * ks];
                uint32_t a2 = phi01[2 * ks + 1], a3 = phi23[2 * ks + 1];
                mma16816(o[n], a0, a1, a2, a3, b0h, b1h);
                mma16816(o[n], a0, a1, a2, a3, b0l, b1l);
                mma16816(o[n], plo01[2 * ks], plo23[2 * ks],
                               plo01[2 * ks + 1], plo23[2 * ks + 1], b0h, b1h);
            }
        }
        __syncthreads();
    }

    l0 += __shfl_xor_sync(0xffffffffu, l0, 1);
    l0 += __shfl_xor_sync(0xffffffffu, l0, 2);
    l1 += __shfl_xor_sync(0xffffffffu, l1, 1);
    l1 += __shfl_xor_sync(0xffffffffu, l1, 2);
    const float inv0 = 1.0f / l0;
    const float inv1 = 1.0f / l1;

    // store O split-bf16 into g_oh/g_ol [B*S, E]
    const int b = bh >> 3, h = bh & 7;
    const int r1g = r0g + 8;
    #pragma unroll
    for (int n = 0; n < 4; n++) {
        int p = 8 * n + 2 * tig;
        if (v0) {
            float w0 = o[n][0] * inv0, w1 = o[n][1] * inv0;
            size_t idx = ((size_t)b * S_LEN + r0g) * E_DIM + h * P_DIM + p;
            uint32_t ph = pack_bf16x2(w0, w1);
            *(uint32_t*)&g_oh[idx] = ph;
            *(uint32_t*)&g_ol[idx] = pack_bf16x2(w0 - __uint_as_float(ph << 16),
                                                 w1 - __uint_as_float(ph & 0xffff0000u));
        }
        if (v1) {
            float w0 = o[n][2] * inv1, w1 = o[n][3] * inv1;
            size_t idx = ((size_t)b * S_LEN + r1g) * E_DIM + h * P_DIM + p;
            uint32_t ph = pack_bf16x2(w0, w1);
            *(uint32_t*)&g_oh[idx] = ph;
            *(uint32_t*)&g_ol[idx] = pack_bf16x2(w0 - __uint_as_float(ph << 16),
                                                 w1 - __uint_as_float(ph & 0xffff0000u));
        }
    }
}

// ---------------------------------------------------------------------------
// Kernel 3: output projection on tensor cores. grid (27, 4), block 256.
// ---------------------------------------------------------------------------
__global__ __launch_bounds__(256) void out_mma_kernel(
    const float* __restrict__ bo, float* __restrict__ out)
{
    __shared__ __nv_bfloat16 Ah[128][40], Al[128][40];
    __shared__ __nv_bfloat16 Bh[64][40], Bl[64][40];

    const int tid = threadIdx.x;
    const int warp = tid >> 5, lane = tid & 31;
    const int g = lane >> 2, tig = lane & 3;
    const int wm = warp >> 1, wn = warp & 1;
    const int m0 = blockIdx.x * 128;
    const int n0 = blockIdx.y * 64;

    const __nv_bfloat16* wth = g_wth + (size_t)3 * E_DIM * E_DIM;
    const __nv_bfloat16* wtl = g_wtl + (size_t)3 * E_DIM * E_DIM;

    float c[2][4][4] = {};

    for (int k0 = 0; k0 < E_DIM; k0 += 32) {
        #pragma unroll
        for (int i = 0; i < 2; i++) {
            int e = tid + i * 256;
            int r = e >> 2, cc = (e & 3) * 8;
            *(uint4*)&Ah[r][cc] = *(const uint4*)&g_oh[(size_t)(m0 + r) * E_DIM + k0 + cc];
            *(uint4*)&Al[r][cc] = *(const uint4*)&g_ol[(size_t)(m0 + r) * E_DIM + k0 + cc];
        }
        {
            int r = tid >> 2, cc = (tid & 3) * 8;
            *(uint4*)&Bh[r][cc] = *(const uint4*)&wth[(size_t)(n0 + r) * E_DIM + k0 + cc];
            *(uint4*)&Bl[r][cc] = *(const uint4*)&wtl[(size_t)(n0 + r) * E_DIM + k0 + cc];
        }
        __syncthreads();

        uint32_t ah[2][2][4], al[2][2][4];
        #pragma unroll
        for (int mf = 0; mf < 2; mf++) {
            int r = wm * 32 + mf * 16 + g;
            #pragma unroll
            for (int ks = 0; ks < 2; ks++) {
                int p0 = ks * 16 + 2 * tig;
                ah[mf][ks][0] = *(const uint32_t*)&Ah[r][p0];
                ah[mf][ks][1] = *(const uint32_t*)&Ah[r + 8][p0];
                ah[mf][ks][2] = *(const uint32_t*)&Ah[r][p0 + 8];
                ah[mf][ks][3] = *(const uint32_t*)&Ah[r + 8][p0 + 8];
                al[mf][ks][0] = *(const uint32_t*)&Al[r][p0];
                al[mf][ks][1] = *(const uint32_t*)&Al[r + 8][p0];
                al[mf][ks][2] = *(const uint32_t*)&Al[r][p0 + 8];
                al[mf][ks][3] = *(const uint32_t*)&Al[r + 8][p0 + 8];
            }
        }
        #pragma unroll
        for (int nf = 0; nf < 4; nf++) {
            int col = wn * 32 + nf * 8 + g;
            uint32_t bh[2][2], bl[2][2];
            #pragma unroll
            for (int ks = 0; ks < 2; ks++) {
                int p0 = ks * 16 + 2 * tig;
                bh[ks][0] = *(const uint32_t*)&Bh[col][p0];
                bh[ks][1] = *(const uint32_t*)&Bh[col][p0 + 8];
                bl[ks][0] = *(const uint32_t*)&Bl[col][p0];
                bl[ks][1] = *(const uint32_t*)&Bl[col][p0 + 8];
            }
            #pragma unroll
            for (int mf = 0; mf < 2; mf++) {
                #pragma unroll
                for (int ks = 0; ks < 2; ks++) {
                    mma16816(c[mf][nf], ah[mf][ks][0], ah[mf][ks][1],
                             ah[mf][ks][2], ah[mf][ks][3], bh[ks][0], bh[ks][1]);
                    mma16816(c[mf][nf], al[mf][ks][0], al[mf][ks][1],
                             al[mf][ks][2], al[mf][ks][3], bh[ks][0], bh[ks][1]);
                    mma16816(c[mf][nf], ah[mf][ks][0], ah[mf][ks][1],
                             ah[mf][ks][2], ah[mf][ks][3], bl[ks][0], bl[ks][1]);
                }
            }
        }
        __syncthreads();
    }

    #pragma unroll
    for (int mf = 0; mf < 2; mf++) {
        int r0 = m0 + wm * 32 + mf * 16 + g;
        int r1 = r0 + 8;
        #pragma unroll
        for (int nf = 0; nf < 4; nf++) {
            int n = n0 + wn * 32 + nf * 8 + 2 * tig;
            float b0 = bo[n], b1 = bo[n + 1];
            *(float2*)&out[(size_t)r0 * E_DIM + n] =
                make_float2(c[mf][nf][0] + b0, c[mf][nf][1] + b1);
            *(float2*)&out[(size_t)r1 * E_DIM + n] =
                make_float2(c[mf][nf][2] + b0, c[mf][nf][3] + b1);
        }
    }
}

extern "C" void kernel_launch(void* const* d_in, const int* in_sizes, int n_in,
                              void* d_out, int out_size)
{
    const float* x  = (const float*)d_in[0];
    const float* bq = (const float*)d_in[2];
    const float* bk = (const float*)d_in[4];
    const float* bv = (const float*)d_in[6];
    const float* bo = (const float*)d_in[8];
    float* out = (float*)d_out;

    prep_x_kernel<<<M_ROWS * E_DIM / 1024, 256>>>(x);
    prep_w_kernel<<<dim3(8, 8, 4), 256>>>(
        (const float*)d_in[1], (const float*)d_in[3],
        (const float*)d_in[5], (const float*)d_in[7]);
    qkv_mma_kernel<<<dim3(27, 4, 3), 256>>>(bq, bk, bv);
    attn_mma_kernel<<<dim3(14, 16), 256>>>();
    out_mma_kernel<<<dim3(27, 4), 256>>>(bo, out);
}

// round 12
// speedup vs baseline: 2.8933x; 1.1232x over previous
#include <cuda_runtime.h>
#include <cuda_bf16.h>
#include <cstdint>

#define S_LEN 1728
#define B_SZ 2
#define E_DIM 256
#define H_NUM 8
#define P_DIM 32
#define M_ROWS (B_SZ * S_LEN)   // 3456

#define QT 96                   // q rows per block (attn): 18 tiles exactly
#define ATW 6                   // attn warps per block
#define ATT (ATW * 32)          // 192 threads
#define KN 64                   // keys per tile (attn)
#define NKT (S_LEN / KN)        // 27

#define LOG2E 1.44269504088896340736f

// split-bf16 scratch (no allocations allowed)
__device__ __align__(16) __nv_bfloat16 g_qh[B_SZ * H_NUM * S_LEN * P_DIM]; // [B,H,S,P]
__device__ __align__(16) __nv_bfloat16 g_ql[B_SZ * H_NUM * S_LEN * P_DIM];
__device__ __align__(16) __nv_bfloat16 g_kh[B_SZ * H_NUM * S_LEN * P_DIM];
__device__ __align__(16) __nv_bfloat16 g_kl[B_SZ * H_NUM * S_LEN * P_DIM];
__device__ __align__(16) __nv_bfloat16 g_vth[B_SZ * H_NUM * P_DIM * S_LEN]; // [B,H,P,S]
__device__ __align__(16) __nv_bfloat16 g_vtl[B_SZ * H_NUM * P_DIM * S_LEN];
__device__ __align__(16) __nv_bfloat16 g_xh[M_ROWS * E_DIM];
__device__ __align__(16) __nv_bfloat16 g_xl[M_ROWS * E_DIM];
__device__ __align__(16) __nv_bfloat16 g_wth[4 * E_DIM * E_DIM];  // Wt[n][k], z=q,k,v,o
__device__ __align__(16) __nv_bfloat16 g_wtl[4 * E_DIM * E_DIM];
__device__ __align__(16) __nv_bfloat16 g_oh[M_ROWS * E_DIM];      // attn out hi
__device__ __align__(16) __nv_bfloat16 g_ol[M_ROWS * E_DIM];      // attn out lo

// ---------------------------------------------------------------------------
// helpers
// ---------------------------------------------------------------------------
__device__ __forceinline__ void mma16816(float c[4],
    uint32_t a0, uint32_t a1, uint32_t a2, uint32_t a3,
    uint32_t b0, uint32_t b1)
{
    asm volatile(
        "mma.sync.aligned.m16n8k16.row.col.f32.bf16.bf16.f32 "
        "{%0,%1,%2,%3}, {%4,%5,%6,%7}, {%8,%9}, {%0,%1,%2,%3};"
        : "+f"(c[0]), "+f"(c[1]), "+f"(c[2]), "+f"(c[3])
        : "r"(a0), "r"(a1), "r"(a2), "r"(a3), "r"(b0), "r"(b1));
}

__device__ __forceinline__ void ldsm_x4(uint32_t r[4], uint32_t addr) {
    asm volatile("ldmatrix.sync.aligned.m8n8.x4.shared.b16 {%0,%1,%2,%3}, [%4];"
                 : "=r"(r[0]), "=r"(r[1]), "=r"(r[2]), "=r"(r[3]) : "r"(addr));
}

__device__ __forceinline__ uint32_t smem_u32(const void* p) {
    uint32_t a;
    asm("{ .reg .u64 t; cvta.to.shared.u64 t, %1; cvt.u32.u64 %0, t; }"
        : "=r"(a) : "l"(p));
    return a;
}
__device__ __forceinline__ void cp16(uint32_t saddr, const void* g) {
    asm volatile("cp.async.cg.shared.global [%0], [%1], 16;"
                 :: "r"(saddr), "l"(g) : "memory");
}
#define CP_COMMIT() asm volatile("cp.async.commit_group;" ::: "memory")
#define CP_WAIT(N)  asm volatile("cp.async.wait_group %0;" :: "n"(N) : "memory")

__device__ __forceinline__ float ex2f(float x) {
    float y;
    asm("ex2.approx.ftz.f32 %0, %1;" : "=f"(y) : "f"(x));
    return y;
}
// pack (lo, hi) floats into bf16x2 register
__device__ __forceinline__ uint32_t pack_bf16x2(float lo, float hi) {
    uint32_t r;
    asm("cvt.rn.bf16x2.f32 %0, %1, %2;" : "=r"(r) : "f"(hi), "f"(lo));
    return r;
}
__device__ __forceinline__ void split2(float v, __nv_bfloat16& h, __nv_bfloat16& l) {
    h = __float2bfloat16(v);
    l = __float2bfloat16(v - __bfloat162float(h));
}

// ---------------------------------------------------------------------------
// Prep 1: split x -> g_xh/g_xl. grid 864, block 256.
// ---------------------------------------------------------------------------
__global__ __launch_bounds__(256) void prep_x_kernel(const float* __restrict__ x)
{
    int i = (blockIdx.x * 256 + threadIdx.x) * 4;
    float4 v = *(const float4*)&x[i];
    uint2 hi, lo;
    hi.x = pack_bf16x2(v.x, v.y);
    hi.y = pack_bf16x2(v.z, v.w);
    lo.x = pack_bf16x2(v.x - __uint_as_float(hi.x << 16),
                       v.y - __uint_as_float(hi.x & 0xffff0000u));
    lo.y = pack_bf16x2(v.z - __uint_as_float(hi.y << 16),
                       v.w - __uint_as_float(hi.y & 0xffff0000u));
    *(uint2*)&g_xh[i] = hi;
    *(uint2*)&g_xl[i] = lo;
}

// ---------------------------------------------------------------------------
// Prep 2: transpose + split weights -> g_wth/g_wtl. grid (8, 8, 4), block 256.
// ---------------------------------------------------------------------------
__global__ __launch_bounds__(256) void prep_w_kernel(
    const float* __restrict__ Wq, const float* __restrict__ Wk,
    const float* __restrict__ Wv, const float* __restrict__ Wo)
{
    __shared__ float s[32][33];
    const int z = blockIdx.z;
    const float* W = (z == 0) ? Wq : (z == 1) ? Wk : (z == 2) ? Wv : Wo;
    const int k0 = blockIdx.x * 32, n0 = blockIdx.y * 32;
    const int c = threadIdx.x & 31, r0 = threadIdx.x >> 5;
    #pragma unroll
    for (int i = 0; i < 4; i++) {
        int r = r0 + i * 8;
        s[r][c] = W[(k0 + r) * E_DIM + n0 + c];
    }
    __syncthreads();
    #pragma unroll
    for (int i = 0; i < 4; i++) {
        int r = r0 + i * 8;
        float v = s[c][r];
        __nv_bfloat16 h, l; split2(v, h, l);
        size_t idx = (size_t)z * E_DIM * E_DIM + (size_t)(n0 + r) * E_DIM + k0 + c;
        g_wth[idx] = h;
        g_wtl[idx] = l;
    }
}

// ---------------------------------------------------------------------------
// Kernel 1: QKV projection, bf16-split 3-MMA. grid (27, 4, 3), block 256.
// Q outputs are prescaled by log2(e) so attention can use bare ex2.
// V stored transposed [B,H,P,S].
// ---------------------------------------------------------------------------
__global__ __launch_bounds__(256) void qkv_mma_kernel(
    const float* __restrict__ bq, const float* __restrict__ bk,
    const float* __restrict__ bv)
{
    __shared__ __nv_bfloat16 Ah[128][40], Al[128][40];
    __shared__ __nv_bfloat16 Bh[64][40], Bl[64][40];

    const int tid = threadIdx.x;
    const int warp = tid >> 5, lane = tid & 31;
    const int g = lane >> 2, tig = lane & 3;
    const int wm = warp >> 1, wn = warp & 1;
    const int m0 = blockIdx.x * 128;
    const int n0 = blockIdx.y * 64;
    const int z  = blockIdx.z;

    const __nv_bfloat16* wth = g_wth + (size_t)z * E_DIM * E_DIM;
    const __nv_bfloat16* wtl = g_wtl + (size_t)z * E_DIM * E_DIM;
    const float* bias = (z == 0) ? bq : (z == 1) ? bk : bv;
    const float outscale = (z == 0) ? LOG2E : 1.0f;

    float c[2][4][4] = {};

    for (int k0 = 0; k0 < E_DIM; k0 += 32) {
        #pragma unroll
        for (int i = 0; i < 2; i++) {
            int e = tid + i * 256;
            int r = e >> 2, cc = (e & 3) * 8;
            *(uint4*)&Ah[r][cc] = *(const uint4*)&g_xh[(size_t)(m0 + r) * E_DIM + k0 + cc];
            *(uint4*)&Al[r][cc] = *(const uint4*)&g_xl[(size_t)(m0 + r) * E_DIM + k0 + cc];
        }
        {
            int r = tid >> 2, cc = (tid & 3) * 8;
            *(uint4*)&Bh[r][cc] = *(const uint4*)&wth[(size_t)(n0 + r) * E_DIM + k0 + cc];
            *(uint4*)&Bl[r][cc] = *(const uint4*)&wtl[(size_t)(n0 + r) * E_DIM + k0 + cc];
        }
        __syncthreads();

        uint32_t ah[2][2][4], al[2][2][4];
        #pragma unroll
        for (int mf = 0; mf < 2; mf++) {
            int r = wm * 32 + mf * 16 + g;
            #pragma unroll
            for (int ks = 0; ks < 2; ks++) {
                int p0 = ks * 16 + 2 * tig;
                ah[mf][ks][0] = *(const uint32_t*)&Ah[r][p0];
                ah[mf][ks][1] = *(const uint32_t*)&Ah[r + 8][p0];
                ah[mf][ks][2] = *(const uint32_t*)&Ah[r][p0 + 8];
                ah[mf][ks][3] = *(const uint32_t*)&Ah[r + 8][p0 + 8];
                al[mf][ks][0] = *(const uint32_t*)&Al[r][p0];
                al[mf][ks][1] = *(const uint32_t*)&Al[r + 8][p0];
                al[mf][ks][2] = *(const uint32_t*)&Al[r][p0 + 8];
                al[mf][ks][3] = *(const uint32_t*)&Al[r + 8][p0 + 8];
            }
        }
        #pragma unroll
        for (int nf = 0; nf < 4; nf++) {
            int col = wn * 32 + nf * 8 + g;
            uint32_t bh[2][2], bl[2][2];
            #pragma unroll
            for (int ks = 0; ks < 2; ks++) {
                int p0 = ks * 16 + 2 * tig;
                bh[ks][0] = *(const uint32_t*)&Bh[col][p0];
                bh[ks][1] = *(const uint32_t*)&Bh[col][p0 + 8];
                bl[ks][0] = *(const uint32_t*)&Bl[col][p0];
                bl[ks][1] = *(const uint32_t*)&Bl[col][p0 + 8];
            }
            #pragma unroll
            for (int mf = 0; mf < 2; mf++) {
                #pragma unroll
                for (int ks = 0; ks < 2; ks++) {
                    mma16816(c[mf][nf], ah[mf][ks][0], ah[mf][ks][1],
                             ah[mf][ks][2], ah[mf][ks][3], bh[ks][0], bh[ks][1]);
                    mma16816(c[mf][nf], al[mf][ks][0], al[mf][ks][1],
                             al[mf][ks][2], al[mf][ks][3], bh[ks][0], bh[ks][1]);
                    mma16816(c[mf][nf], ah[mf][ks][0], ah[mf][ks][1],
                             ah[mf][ks][2], ah[mf][ks][3], bl[ks][0], bl[ks][1]);
                }
            }
        }
        __syncthreads();
    }

    // epilogue: + bias, optional log2e scale, split to bf16 hi/lo, store
    #pragma unroll
    for (int mf = 0; mf < 2; mf++) {
        int rr[2] = { m0 + wm * 32 + mf * 16 + g, m0 + wm * 32 + mf * 16 + g + 8 };
        #pragma unroll
        for (int nf = 0; nf < 4; nf++) {
            int n = n0 + wn * 32 + nf * 8 + 2 * tig;
            int h = n >> 5, p = n & 31;
            float b0 = bias[n], b1 = bias[n + 1];
            #pragma unroll
            for (int half = 0; half < 2; half++) {
                int m = rr[half];
                int bb = m / S_LEN, s = m % S_LEN;
                float v0 = (c[mf][nf][2 * half] + b0) * outscale;
                float v1 = (c[mf][nf][2 * half + 1] + b1) * outscale;
                __nv_bfloat16 h0, l0, h1, l1;
                split2(v0, h0, l0); split2(v1, h1, l1);
                if (z == 2) {
                    size_t tb = ((size_t)(bb * H_NUM + h) * P_DIM + p) * S_LEN + s;
                    g_vth[tb] = h0; g_vth[tb + S_LEN] = h1;
                    g_vtl[tb] = l0; g_vtl[tb + S_LEN] = l1;
                } else {
                    size_t idx = ((size_t)(bb * H_NUM + h) * S_LEN + s) * P_DIM + p;
                    uint32_t ph = ((uint32_t)__bfloat16_as_ushort(h1) << 16) |
                                  __bfloat16_as_ushort(h0);
                    uint32_t pl = ((uint32_t)__bfloat16_as_ushort(l1) << 16) |
                                  __bfloat16_as_ushort(l0);
                    if (z == 0) { *(uint32_t*)&g_qh[idx] = ph; *(uint32_t*)&g_ql[idx] = pl; }
                    else        { *(uint32_t*)&g_kh[idx] = ph; *(uint32_t*)&g_kl[idx] = pl; }
                }
            }
        }
    }
}

// ---------------------------------------------------------------------------
// Kernel 2: flash attention; pre-split operands, cp.async double buffering,
// ldmatrix B-fragments, log2-domain softmax.
// grid = (18, 16), block = 192 (6 warps, warp = 16 q rows, QT = 96).
// 288 CTAs -> near-uniform 2 CTAs/SM (balanced wave).
// ---------------------------------------------------------------------------
__global__ __launch_bounds__(ATT, 2) void attn_mma_kernel()
{
    __shared__ __nv_bfloat16 Kh[2][KN][40], Kl[2][KN][40];
    __shared__ __nv_bfloat16 Vth[2][P_DIM][72], Vtl[2][P_DIM][72];

    const int tid  = threadIdx.x;
    const int warp = tid >> 5, lane = tid & 31;
    const int g    = lane >> 2, tig = lane & 3;
    const int l8   = lane & 7, lq = lane >> 3;
    const int woff = warp * 16;
    const int bh   = blockIdx.y;
    const int q0   = blockIdx.x * QT;

    const size_t bhSP = (size_t)bh * S_LEN * P_DIM;
    const size_t bhPS = (size_t)bh * P_DIM * S_LEN;

    // ldmatrix per-lane base addresses (rows l8, col block 8*lq)
    uint32_t aKh[2], aKl[2], aVh[2], aVl[2];
    #pragma unroll
    for (int b = 0; b < 2; b++) {
        aKh[b] = smem_u32(&Kh[b][l8][8 * lq]);
        aKl[b] = smem_u32(&Kl[b][l8][8 * lq]);
        aVh[b] = smem_u32(&Vth[b][l8][8 * lq]);
        aVl[b] = smem_u32(&Vtl[b][l8][8 * lq]);
    }

    // cp.async tile loader: strided loops over 16B chunks (192 threads)
    #define LOAD_TILE(kt, b) do {                                               \
        int _k0 = (kt) * KN;                                                    \
        for (int i = tid; i < KN * 4; i += ATT) {                               \
            int r = i >> 2, c = (i & 3) * 8;                                    \
            cp16(smem_u32(&Kh[b][r][c]),                                        \
                 &g_kh[bhSP + (size_t)(_k0 + r) * P_DIM + c]);                  \
            cp16(smem_u32(&Kl[b][r][c]),                                        \
                 &g_kl[bhSP + (size_t)(_k0 + r) * P_DIM + c]);                  \
        }                                                                       \
        for (int i = tid; i < P_DIM * 8; i += ATT) {                            \
            int p = i >> 3, c = (i & 7) * 8;                                    \
            cp16(smem_u32(&Vth[b][p][c]),                                       \
                 &g_vth[bhPS + (size_t)p * S_LEN + _k0 + c]);                   \
            cp16(smem_u32(&Vtl[b][p][c]),                                       \
                 &g_vtl[bhPS + (size_t)p * S_LEN + _k0 + c]);                   \
        }                                                                       \
    } while (0)

    LOAD_TILE(0, 0);
    CP_COMMIT();

    // Q fragments straight from global (all rows valid: 18*96 == S_LEN)
    const int r0g = q0 + woff + g;
    const size_t qb0 = bhSP + (size_t)r0g * P_DIM;
    const size_t qb1 = qb0 + 8 * P_DIM;
    uint32_t qh[2][4], ql[2][4];
    #pragma unroll
    for (int ks = 0; ks < 2; ks++) {
        int p0 = ks * 16 + 2 * tig;
        qh[ks][0] = *(const uint32_t*)&g_qh[qb0 + p0];
        qh[ks][1] = *(const uint32_t*)&g_qh[qb1 + p0];
        qh[ks][2] = *(const uint32_t*)&g_qh[qb0 + p0 + 8];
        qh[ks][3] = *(const uint32_t*)&g_qh[qb1 + p0 + 8];
        ql[ks][0] = *(const uint32_t*)&g_ql[qb0 + p0];
        ql[ks][1] = *(const uint32_t*)&g_ql[qb1 + p0];
        ql[ks][2] = *(const uint32_t*)&g_ql[qb0 + p0 + 8];
        ql[ks][3] = *(const uint32_t*)&g_ql[qb1 + p0 + 8];
    }

    float o[4][4] = {};
    float l0 = 0.f, l1 = 0.f;

    for (int kt = 0; kt < NKT; kt++) {
        const int buf = kt & 1;
        if (kt + 1 < NKT) {
            LOAD_TILE(kt + 1, buf ^ 1);
            CP_COMMIT();
            CP_WAIT(1);
        } else {
            CP_WAIT(0);
        }
        __syncthreads();

        // scores (16x64 per warp): ldmatrix x4 gives b-frags for both ksteps
        uint32_t phi01[8], phi23[8], plo01[8], plo23[8];
        #pragma unroll
        for (int nt = 0; nt < 8; nt++) {
            uint32_t kh4[4], kl4[4];
            ldsm_x4(kh4, aKh[buf] + nt * (8 * 40 * 2));
            ldsm_x4(kl4, aKl[buf] + nt * (8 * 40 * 2));
            float c[4] = {0.f, 0.f, 0.f, 0.f};
            mma16816(c, qh[0][0], qh[0][1], qh[0][2], qh[0][3], kh4[0], kh4[1]);
            mma16816(c, ql[0][0], ql[0][1], ql[0][2], ql[0][3], kh4[0], kh4[1]);
            mma16816(c, qh[0][0], qh[0][1], qh[0][2], qh[0][3], kl4[0], kl4[1]);
            mma16816(c, qh[1][0], qh[1][1], qh[1][2], qh[1][3], kh4[2], kh4[3]);
            mma16816(c, ql[1][0], ql[1][1], ql[1][2], ql[1][3], kh4[2], kh4[3]);
            mma16816(c, qh[1][0], qh[1][1], qh[1][2], qh[1][3], kl4[2], kl4[3]);

            // scores are log2-domain: p = 2^s
            float e0 = ex2f(c[0]);
            float e1 = ex2f(c[1]);
            float e2 = ex2f(c[2]);
            float e3 = ex2f(c[3]);
            l0 += e0 + e1;
            l1 += e2 + e3;
            uint32_t ph01 = pack_bf16x2(e0, e1);
            uint32_t ph23 = pack_bf16x2(e2, e3);
            phi01[nt] = ph01;
            phi23[nt] = ph23;
            plo01[nt] = pack_bf16x2(e0 - __uint_as_float(ph01 << 16),
                                    e1 - __uint_as_float(ph01 & 0xffff0000u));
            plo23[nt] = pack_bf16x2(e2 - __uint_as_float(ph23 << 16),
                                    e3 - __uint_as_float(ph23 & 0xffff0000u));
        }

        // PV: O(16x32) += P(16x64) @ V(64x32); ldmatrix covers 2 ksteps per x4
        #pragma unroll
        for (int n = 0; n < 4; n++) {
            uint32_t vhA[4], vhB[4], vlA[4], vlB[4];
            uint32_t base = n * (8 * 72 * 2);
            ldsm_x4(vhA, aVh[buf] + base);
            ldsm_x4(vhB, aVh[buf] + base + 64);
            ldsm_x4(vlA, aVl[buf] + base);
            ldsm_x4(vlB, aVl[buf] + base + 64);
            #pragma unroll
            for (int ks = 0; ks < 4; ks++) {
                uint32_t b0h = (ks < 2 ? vhA : vhB)[2 * (ks & 1)];
                uint32_t b1h = (ks < 2 ? vhA : vhB)[2 * (ks & 1) + 1];
                uint32_t b0l = (ks < 2 ? vlA : vlB)[2 * (ks & 1)];
                uint32_t b1l = (ks < 2 ? vlA : vlB)[2 * (ks & 1) + 1];
                uint32_t a0 = phi01[2 * ks], a1 = phi23[2 * ks];
                uint32_t a2 = phi01[2 * ks + 1], a3 = phi23[2 * ks + 1];
                mma16816(o[n], a0, a1, a2, a3, b0h, b1h);
                mma16816(o[n], a0, a1, a2, a3, b0l, b1l);
                mma16816(o[n], plo01[2 * ks], plo23[2 * ks],
                               plo01[2 * ks + 1], plo23[2 * ks + 1], b0h, b1h);
            }
        }
        __syncthreads();
    }

    l0 += __shfl_xor_sync(0xffffffffu, l0, 1);
    l0 += __shfl_xor_sync(0xffffffffu, l0, 2);
    l1 += __shfl_xor_sync(0xffffffffu, l1, 1);
    l1 += __shfl_xor_sync(0xffffffffu, l1, 2);
    const float inv0 = 1.0f / l0;
    const float inv1 = 1.0f / l1;

    // store O split-bf16 into g_oh/g_ol [B*S, E]
    const int b = bh >> 3, h = bh & 7;
    const int r1g = r0g + 8;
    #pragma unroll
    for (int n = 0; n < 4; n++) {
        int p = 8 * n + 2 * tig;
        {
            float w0 = o[n][0] * inv0, w1 = o[n][1] * inv0;
            size_t idx = ((size_t)b * S_LEN + r0g) * E_DIM + h * P_DIM + p;
            uint32_t ph = pack_bf16x2(w0, w1);
            *(uint32_t*)&g_oh[idx] = ph;
            *(uint32_t*)&g_ol[idx] = pack_bf16x2(w0 - __uint_as_float(ph << 16),
                                                 w1 - __uint_as_float(ph & 0xffff0000u));
        }
        {
            float w0 = o[n][2] * inv1, w1 = o[n][3] * inv1;
            size_t idx = ((size_t)b * S_LEN + r1g) * E_DIM + h * P_DIM + p;
            uint32_t ph = pack_bf16x2(w0, w1);
            *(uint32_t*)&g_oh[idx] = ph;
            *(uint32_t*)&g_ol[idx] = pack_bf16x2(w0 - __uint_as_float(ph << 16),
                                                 w1 - __uint_as_float(ph & 0xffff0000u));
        }
    }
}

// ---------------------------------------------------------------------------
// Kernel 3: output projection on tensor cores. grid (27, 4), block 256.
// ---------------------------------------------------------------------------
__global__ __launch_bounds__(256) void out_mma_kernel(
    const float* __restrict__ bo, float* __restrict__ out)
{
    __shared__ __nv_bfloat16 Ah[128][40], Al[128][40];
    __shared__ __nv_bfloat16 Bh[64][40], Bl[64][40];

    const int tid = threadIdx.x;
    const int warp = tid >> 5, lane = tid & 31;
    const int g = lane >> 2, tig = lane & 3;
    const int wm = warp >> 1, wn = warp & 1;
    const int m0 = blockIdx.x * 128;
    const int n0 = blockIdx.y * 64;

    const __nv_bfloat16* wth = g_wth + (size_t)3 * E_DIM * E_DIM;
    const __nv_bfloat16* wtl = g_wtl + (size_t)3 * E_DIM * E_DIM;

    float c[2][4][4] = {};

    for (int k0 = 0; k0 < E_DIM; k0 += 32) {
        #pragma unroll
        for (int i = 0; i < 2; i++) {
            int e = tid + i * 256;
            int r = e >> 2, cc = (e & 3) * 8;
            *(uint4*)&Ah[r][cc] = *(const uint4*)&g_oh[(size_t)(m0 + r) * E_DIM + k0 + cc];
            *(uint4*)&Al[r][cc] = *(const uint4*)&g_ol[(size_t)(m0 + r) * E_DIM + k0 + cc];
        }
        {
            int r = tid >> 2, cc = (tid & 3) * 8;
            *(uint4*)&Bh[r][cc] = *(const uint4*)&wth[(size_t)(n0 + r) * E_DIM + k0 + cc];
            *(uint4*)&Bl[r][cc] = *(const uint4*)&wtl[(size_t)(n0 + r) * E_DIM + k0 + cc];
        }
        __syncthreads();

        uint32_t ah[2][2][4], al[2][2][4];
        #pragma unroll
        for (int mf = 0; mf < 2; mf++) {
            int r = wm * 32 + mf * 16 + g;
            #pragma unroll
            for (int ks = 0; ks < 2; ks++) {
                int p0 = ks * 16 + 2 * tig;
                ah[mf][ks][0] = *(const uint32_t*)&Ah[r][p0];
                ah[mf][ks][1] = *(const uint32_t*)&Ah[r + 8][p0];
                ah[mf][ks][2] = *(const uint32_t*)&Ah[r][p0 + 8];
                ah[mf][ks][3] = *(const uint32_t*)&Ah[r + 8][p0 + 8];
                al[mf][ks][0] = *(const uint32_t*)&Al[r][p0];
                al[mf][ks][1] = *(const uint32_t*)&Al[r + 8][p0];
                al[mf][ks][2] = *(const uint32_t*)&Al[r][p0 + 8];
                al[mf][ks][3] = *(const uint32_t*)&Al[r + 8][p0 + 8];
            }
        }
        #pragma unroll
        for (int nf = 0; nf < 4; nf++) {
            int col = wn * 32 + nf * 8 + g;
            uint32_t bh[2][2], bl[2][2];
            #pragma unroll
            for (int ks = 0; ks < 2; ks++) {
                int p0 = ks * 16 + 2 * tig;
                bh[ks][0] = *(const uint32_t*)&Bh[col][p0];
                bh[ks][1] = *(const uint32_t*)&Bh[col][p0 + 8];
                bl[ks][0] = *(const uint32_t*)&Bl[col][p0];
                bl[ks][1] = *(const uint32_t*)&Bl[col][p0 + 8];
            }
            #pragma unroll
            for (int mf = 0; mf < 2; mf++) {
                #pragma unroll
                for (int ks = 0; ks < 2; ks++) {
                    mma16816(c[mf][nf], ah[mf][ks][0], ah[mf][ks][1],
                             ah[mf][ks][2], ah[mf][ks][3], bh[ks][0], bh[ks][1]);
                    mma16816(c[mf][nf], al[mf][ks][0], al[mf][ks][1],
                             al[mf][ks][2], al[mf][ks][3], bh[ks][0], bh[ks][1]);
                    mma16816(c[mf][nf], ah[mf][ks][0], ah[mf][ks][1],
                             ah[mf][ks][2], ah[mf][ks][3], bl[ks][0], bl[ks][1]);
                }
            }
        }
        __syncthreads();
    }

    #pragma unroll
    for (int mf = 0; mf < 2; mf++) {
        int r0 = m0 + wm * 32 + mf * 16 + g;
        int r1 = r0 + 8;
        #pragma unroll
        for (int nf = 0; nf < 4; nf++) {
            int n = n0 + wn * 32 + nf * 8 + 2 * tig;
            float b0 = bo[n], b1 = bo[n + 1];
            *(float2*)&out[(size_t)r0 * E_DIM + n] =
                make_float2(c[mf][nf][0] + b0, c[mf][nf][1] + b1);
            *(float2*)&out[(size_t)r1 * E_DIM + n] =
                make_float2(c[mf][nf][2] + b0, c[mf][nf][3] + b1);
        }
    }
}

extern "C" void kernel_launch(void* const* d_in, const int* in_sizes, int n_in,
                              void* d_out, int out_size)
{
    const float* x  = (const float*)d_in[0];
    const float* bq = (const float*)d_in[2];
    const float* bk = (const float*)d_in[4];
    const float* bv = (const float*)d_in[6];
    const float* bo = (const float*)d_in[8];
    float* out = (float*)d_out;

    prep_x_kernel<<<M_ROWS * E_DIM / 1024, 256>>>(x);
    prep_w_kernel<<<dim3(8, 8, 4), 256>>>(
        (const float*)d_in[1], (const float*)d_in[3],
        (const float*)d_in[5], (const float*)d_in[7]);
    qkv_mma_kernel<<<dim3(27, 4, 3), 256>>>(bq, bk, bv);
    attn_mma_kernel<<<dim3(18, 16), ATT>>>();
    out_mma_kernel<<<dim3(27, 4), 256>>>(bo, out);
}

// round 13
// speedup vs baseline: 3.0036x; 1.0381x over previous
#include <cuda_runtime.h>
#include <cuda_bf16.h>
#include <cstdint>

#define S_LEN 1728
#define B_SZ 2
#define E_DIM 256
#define H_NUM 8
#define P_DIM 32
#define M_ROWS (B_SZ * S_LEN)   // 3456

#define QT 96                   // q rows per block (attn): 18 tiles exactly
#define ATW 6                   // attn warps per block
#define ATT (ATW * 32)          // 192 threads
#define KN 64                   // keys per tile (attn)
#define NKT (S_LEN / KN)        // 27

#define LOG2E 1.44269504088896340736f

// GEMM smem ring geometry (elements)
#define GA_ELE (128 * 40)
#define GB_ELE (64 * 40)
#define GBUF_ELE (2 * GA_ELE + 2 * GB_ELE)          // Ah,Al,Bh,Bl
#define GEMM_SMEM_BYTES (3 * GBUF_ELE * 2)          // 3-stage ring, bf16

// split-bf16 scratch (no allocations allowed)
__device__ __align__(16) __nv_bfloat16 g_qh[B_SZ * H_NUM * S_LEN * P_DIM]; // [B,H,S,P]
__device__ __align__(16) __nv_bfloat16 g_ql[B_SZ * H_NUM * S_LEN * P_DIM];
__device__ __align__(16) __nv_bfloat16 g_kh[B_SZ * H_NUM * S_LEN * P_DIM];
__device__ __align__(16) __nv_bfloat16 g_kl[B_SZ * H_NUM * S_LEN * P_DIM];
__device__ __align__(16) __nv_bfloat16 g_vth[B_SZ * H_NUM * P_DIM * S_LEN]; // [B,H,P,S]
__device__ __align__(16) __nv_bfloat16 g_vtl[B_SZ * H_NUM * P_DIM * S_LEN];
__device__ __align__(16) __nv_bfloat16 g_xh[M_ROWS * E_DIM];
__device__ __align__(16) __nv_bfloat16 g_xl[M_ROWS * E_DIM];
__device__ __align__(16) __nv_bfloat16 g_wth[4 * E_DIM * E_DIM];  // Wt[n][k], z=q,k,v,o
__device__ __align__(16) __nv_bfloat16 g_wtl[4 * E_DIM * E_DIM];
__device__ __align__(16) __nv_bfloat16 g_oh[M_ROWS * E_DIM];      // attn out hi
__device__ __align__(16) __nv_bfloat16 g_ol[M_ROWS * E_DIM];      // attn out lo

// ---------------------------------------------------------------------------
// helpers
// ---------------------------------------------------------------------------
__device__ __forceinline__ void mma16816(float c[4],
    uint32_t a0, uint32_t a1, uint32_t a2, uint32_t a3,
    uint32_t b0, uint32_t b1)
{
    asm volatile(
        "mma.sync.aligned.m16n8k16.row.col.f32.bf16.bf16.f32 "
        "{%0,%1,%2,%3}, {%4,%5,%6,%7}, {%8,%9}, {%0,%1,%2,%3};"
        : "+f"(c[0]), "+f"(c[1]), "+f"(c[2]), "+f"(c[3])
        : "r"(a0), "r"(a1), "r"(a2), "r"(a3), "r"(b0), "r"(b1));
}

__device__ __forceinline__ void ldsm_x4(uint32_t r[4], uint32_t addr) {
    asm volatile("ldmatrix.sync.aligned.m8n8.x4.shared.b16 {%0,%1,%2,%3}, [%4];"
                 : "=r"(r[0]), "=r"(r[1]), "=r"(r[2]), "=r"(r[3]) : "r"(addr));
}

__device__ __forceinline__ uint32_t smem_u32(const void* p) {
    uint32_t a;
    asm("{ .reg .u64 t; cvta.to.shared.u64 t, %1; cvt.u32.u64 %0, t; }"
        : "=r"(a) : "l"(p));
    return a;
}
__device__ __forceinline__ void cp16(uint32_t saddr, const void* g) {
    asm volatile("cp.async.cg.shared.global [%0], [%1], 16;"
                 :: "r"(saddr), "l"(g) : "memory");
}
#define CP_COMMIT() asm volatile("cp.async.commit_group;" ::: "memory")
#define CP_WAIT(N)  asm volatile("cp.async.wait_group %0;" :: "n"(N) : "memory")

__device__ __forceinline__ float ex2f(float x) {
    float y;
    asm("ex2.approx.ftz.f32 %0, %1;" : "=f"(y) : "f"(x));
    return y;
}
// pack (lo, hi) floats into bf16x2 register
__device__ __forceinline__ uint32_t pack_bf16x2(float lo, float hi) {
    uint32_t r;
    asm("cvt.rn.bf16x2.f32 %0, %1, %2;" : "=r"(r) : "f"(hi), "f"(lo));
    return r;
}
__device__ __forceinline__ void split2(float v, __nv_bfloat16& h, __nv_bfloat16& l) {
    h = __float2bfloat16(v);
    l = __float2bfloat16(v - __bfloat162float(h));
}

// ---------------------------------------------------------------------------
// Prep 1: split x -> g_xh/g_xl. grid 864, block 256.
// ---------------------------------------------------------------------------
__global__ __launch_bounds__(256) void prep_x_kernel(const float* __restrict__ x)
{
    int i = (blockIdx.x * 256 + threadIdx.x) * 4;
    float4 v = *(const float4*)&x[i];
    uint2 hi, lo;
    hi.x = pack_bf16x2(v.x, v.y);
    hi.y = pack_bf16x2(v.z, v.w);
    lo.x = pack_bf16x2(v.x - __uint_as_float(hi.x << 16),
                       v.y - __uint_as_float(hi.x & 0xffff0000u));
    lo.y = pack_bf16x2(v.z - __uint_as_float(hi.y << 16),
                       v.w - __uint_as_float(hi.y & 0xffff0000u));
    *(uint2*)&g_xh[i] = hi;
    *(uint2*)&g_xl[i] = lo;
}

// ---------------------------------------------------------------------------
// Prep 2: transpose + split weights -> g_wth/g_wtl. grid (8, 8, 4), block 256.
// ---------------------------------------------------------------------------
__global__ __launch_bounds__(256) void prep_w_kernel(
    const float* __restrict__ Wq, const float* __restrict__ Wk,
    const float* __restrict__ Wv, const float* __restrict__ Wo)
{
    __shared__ float s[32][33];
    const int z = blockIdx.z;
    const float* W = (z == 0) ? Wq : (z == 1) ? Wk : (z == 2) ? Wv : Wo;
    const int k0 = blockIdx.x * 32, n0 = blockIdx.y * 32;
    const int c = threadIdx.x & 31, r0 = threadIdx.x >> 5;
    #pragma unroll
    for (int i = 0; i < 4; i++) {
        int r = r0 + i * 8;
        s[r][c] = W[(k0 + r) * E_DIM + n0 + c];
    }
    __syncthreads();
    #pragma unroll
    for (int i = 0; i < 4; i++) {
        int r = r0 + i * 8;
        float v = s[c][r];
        __nv_bfloat16 h, l; split2(v, h, l);
        size_t idx = (size_t)z * E_DIM * E_DIM + (size_t)(n0 + r) * E_DIM + k0 + c;
        g_wth[idx] = h;
        g_wtl[idx] = l;
    }
}

// ---------------------------------------------------------------------------
// Shared GEMM body: C[128,64] = A[128,256] @ Wt[64,256]^T, bf16-split 3-MMA,
// cp.async 3-stage ring + ldmatrix fragments. 256 threads (8 warps 4x2).
// ---------------------------------------------------------------------------
struct GemmFrag {
    float c[2][4][4];
};

__device__ __forceinline__ void gemm_body(
    const __nv_bfloat16* __restrict__ Agh, const __nv_bfloat16* __restrict__ Agl,
    const __nv_bfloat16* __restrict__ wth, const __nv_bfloat16* __restrict__ wtl,
    int m0, int n0, GemmFrag& F)
{
    extern __shared__ __align__(16) char smem_raw[];
    __nv_bfloat16* S = (__nv_bfloat16*)smem_raw;

    const int tid = threadIdx.x;
    const int warp = tid >> 5, lane = tid & 31;
    const int wm = warp >> 1, wn = warp & 1;

    // cp.async chunk coords
    const int ar = tid >> 2, ac = (tid & 3) * 8;       // A: rows 0..63 (x2), 4 chunks
    const int br = tid >> 2, bc = (tid & 3) * 8;       // B: 64 rows, 4 chunks

    // ldmatrix lane addresses (element offsets into a buffer)
    const int aoffA = (wm * 32 + (lane & 7) + ((lane >> 3) & 1) * 8) * 40 + (lane >> 4) * 8;
    const int aoffB = (wn * 32 + (lane & 7)) * 40 + (lane >> 3) * 8;

    #define GLOAD(kk, b) do {                                                  \
        int _k0 = (kk) * 32;                                                   \
        __nv_bfloat16* Ah_ = S + (b) * GBUF_ELE;                               \
        __nv_bfloat16* Al_ = Ah_ + GA_ELE;                                     \
        __nv_bfloat16* Bh_ = Al_ + GA_ELE;                                     \
        __nv_bfloat16* Bl_ = Bh_ + GB_ELE;                                     \
        cp16(smem_u32(Ah_ + ar * 40 + ac),                                     \
             &Agh[(size_t)(m0 + ar) * E_DIM + _k0 + ac]);                      \
        cp16(smem_u32(Ah_ + (ar + 64) * 40 + ac),                              \
             &Agh[(size_t)(m0 + ar + 64) * E_DIM + _k0 + ac]);                 \
        cp16(smem_u32(Al_ + ar * 40 + ac),                                     \
             &Agl[(size_t)(m0 + ar) * E_DIM + _k0 + ac]);                      \
        cp16(smem_u32(Al_ + (ar + 64) * 40 + ac),                              \
             &Agl[(size_t)(m0 + ar + 64) * E_DIM + _k0 + ac]);                 \
        cp16(smem_u32(Bh_ + br * 40 + bc),                                     \
             &wth[(size_t)(n0 + br) * E_DIM + _k0 + bc]);                      \
        cp16(smem_u32(Bl_ + br * 40 + bc),                                     \
             &wtl[(size_t)(n0 + br) * E_DIM + _k0 + bc]);                      \
    } while (0)

    GLOAD(0, 0); CP_COMMIT();
    GLOAD(1, 1); CP_COMMIT();

    #pragma unroll
    for (int mf = 0; mf < 2; mf++)
        #pragma unroll
        for (int nf = 0; nf < 4; nf++)
            #pragma unroll
            for (int i = 0; i < 4; i++)
                F.c[mf][nf][i] = 0.f;

    for (int kk = 0; kk < 8; kk++) {
        const int b = kk % 3;
        CP_WAIT(1);
        __syncthreads();
        if (kk + 2 < 8) { GLOAD(kk + 2, (kk + 2) % 3); CP_COMMIT(); }
        else { CP_COMMIT(); }   // keep group count in sync for CP_WAIT(1)

        __nv_bfloat16* Ah_ = S + b * GBUF_ELE;
        __nv_bfloat16* Al_ = Ah_ + GA_ELE;
        __nv_bfloat16* Bh_ = Al_ + GA_ELE;
        __nv_bfloat16* Bl_ = Bh_ + GB_ELE;
        const uint32_t aA_h = smem_u32(Ah_ + aoffA);
        const uint32_t aA_l = smem_u32(Al_ + aoffA);
        const uint32_t aB_h = smem_u32(Bh_ + aoffB);
        const uint32_t aB_l = smem_u32(Bl_ + aoffB);

        // A fragments: [mf][ks][4]
        uint32_t ah[2][2][4], al[2][2][4];
        #pragma unroll
        for (int mf = 0; mf < 2; mf++) {
            #pragma unroll
            for (int ks = 0; ks < 2; ks++) {
                ldsm_x4(ah[mf][ks], aA_h + mf * (16 * 80) + ks * 32);
                ldsm_x4(al[mf][ks], aA_l + mf * (16 * 80) + ks * 32);
            }
        }
        #pragma unroll
        for (int nf = 0; nf < 4; nf++) {
            uint32_t bh4[4], bl4[4];
            ldsm_x4(bh4, aB_h + nf * (8 * 80));
            ldsm_x4(bl4, aB_l + nf * (8 * 80));
            #pragma unroll
            for (int mf = 0; mf < 2; mf++) {
                #pragma unroll
                for (int ks = 0; ks < 2; ks++) {
                    uint32_t b0h = bh4[2 * ks], b1h = bh4[2 * ks + 1];
                    uint32_t b0l = bl4[2 * ks], b1l = bl4[2 * ks + 1];
                    mma16816(F.c[mf][nf], ah[mf][ks][0], ah[mf][ks][1],
                             ah[mf][ks][2], ah[mf][ks][3], b0h, b1h);
                    mma16816(F.c[mf][nf], al[mf][ks][0], al[mf][ks][1],
                             al[mf][ks][2], al[mf][ks][3], b0h, b1h);
                    mma16816(F.c[mf][nf], ah[mf][ks][0], ah[mf][ks][1],
                             ah[mf][ks][2], ah[mf][ks][3], b0l, b1l);
                }
            }
        }
    }
    CP_WAIT(0);
    #undef GLOAD
}

// ---------------------------------------------------------------------------
// Kernel 1: QKV projection. grid (27, 4, 3), block 256, dynamic smem ring.
// Q prescaled by log2(e); V stored transposed [B,H,P,S].
// ---------------------------------------------------------------------------
__global__ __launch_bounds__(256) void qkv_mma_kernel(
    const float* __restrict__ bq, const float* __restrict__ bk,
    const float* __restrict__ bv)
{
    const int tid = threadIdx.x;
    const int warp = tid >> 5, lane = tid & 31;
    const int g = lane >> 2, tig = lane & 3;
    const int wm = warp >> 1, wn = warp & 1;
    const int m0 = blockIdx.x * 128;
    const int n0 = blockIdx.y * 64;
    const int z  = blockIdx.z;

    const __nv_bfloat16* wth = g_wth + (size_t)z * E_DIM * E_DIM;
    const __nv_bfloat16* wtl = g_wtl + (size_t)z * E_DIM * E_DIM;
    const float* bias = (z == 0) ? bq : (z == 1) ? bk : bv;
    const float outscale = (z == 0) ? LOG2E : 1.0f;

    GemmFrag F;
    gemm_body(g_xh, g_xl, wth, wtl, m0, n0, F);

    // epilogue: + bias, optional log2e scale, split to bf16 hi/lo, store
    #pragma unroll
    for (int mf = 0; mf < 2; mf++) {
        int rr[2] = { m0 + wm * 32 + mf * 16 + g, m0 + wm * 32 + mf * 16 + g + 8 };
        #pragma unroll
        for (int nf = 0; nf < 4; nf++) {
            int n = n0 + wn * 32 + nf * 8 + 2 * tig;
            int h = n >> 5, p = n & 31;
            float b0 = bias[n], b1 = bias[n + 1];
            #pragma unroll
            for (int half = 0; half < 2; half++) {
                int m = rr[half];
                int bb = m / S_LEN, s = m % S_LEN;
                float v0 = (F.c[mf][nf][2 * half] + b0) * outscale;
                float v1 = (F.c[mf][nf][2 * half + 1] + b1) * outscale;
                __nv_bfloat16 h0, l0, h1, l1;
                split2(v0, h0, l0); split2(v1, h1, l1);
                if (z == 2) {
                    size_t tb = ((size_t)(bb * H_NUM + h) * P_DIM + p) * S_LEN + s;
                    g_vth[tb] = h0; g_vth[tb + S_LEN] = h1;
                    g_vtl[tb] = l0; g_vtl[tb + S_LEN] = l1;
                } else {
                    size_t idx = ((size_t)(bb * H_NUM + h) * S_LEN + s) * P_DIM + p;
                    uint32_t ph = ((uint32_t)__bfloat16_as_ushort(h1) << 16) |
                                  __bfloat16_as_ushort(h0);
                    uint32_t pl = ((uint32_t)__bfloat16_as_ushort(l1) << 16) |
                                  __bfloat16_as_ushort(l0);
                    if (z == 0) { *(uint32_t*)&g_qh[idx] = ph; *(uint32_t*)&g_ql[idx] = pl; }
                    else        { *(uint32_t*)&g_kh[idx] = ph; *(uint32_t*)&g_kl[idx] = pl; }
                }
            }
        }
    }
}

// ---------------------------------------------------------------------------
// Kernel 3: output projection. grid (27, 4), block 256, dynamic smem ring.
// ---------------------------------------------------------------------------
__global__ __launch_bounds__(256) void out_mma_kernel(
    const float* __restrict__ bo, float* __restrict__ out)
{
    const int tid = threadIdx.x;
    const int warp = tid >> 5, lane = tid & 31;
    const int g = lane >> 2, tig = lane & 3;
    const int wm = warp >> 1, wn = warp & 1;
    const int m0 = blockIdx.x * 128;
    const int n0 = blockIdx.y * 64;

    const __nv_bfloat16* wth = g_wth + (size_t)3 * E_DIM * E_DIM;
    const __nv_bfloat16* wtl = g_wtl + (size_t)3 * E_DIM * E_DIM;

    GemmFrag F;
    gemm_body(g_oh, g_ol, wth, wtl, m0, n0, F);

    #pragma unroll
    for (int mf = 0; mf < 2; mf++) {
        int r0 = m0 + wm * 32 + mf * 16 + g;
        int r1 = r0 + 8;
        #pragma unroll
        for (int nf = 0; nf < 4; nf++) {
            int n = n0 + wn * 32 + nf * 8 + 2 * tig;
            float b0 = bo[n], b1 = bo[n + 1];
            *(float2*)&out[(size_t)r0 * E_DIM + n] =
                make_float2(F.c[mf][nf][0] + b0, F.c[mf][nf][1] + b1);
            *(float2*)&out[(size_t)r1 * E_DIM + n] =
                make_float2(F.c[mf][nf][2] + b0, F.c[mf][nf][3] + b1);
        }
    }
}

// ---------------------------------------------------------------------------
// Kernel 2: flash attention (unchanged from R12, proven at 62.5us).
// grid = (18, 16), block = 192 (6 warps, warp = 16 q rows, QT = 96).
// ---------------------------------------------------------------------------
__global__ __launch_bounds__(ATT, 2) void attn_mma_kernel()
{
    __shared__ __nv_bfloat16 Kh[2][KN][40], Kl[2][KN][40];
    __shared__ __nv_bfloat16 Vth[2][P_DIM][72], Vtl[2][P_DIM][72];

    const int tid  = threadIdx.x;
    const int warp = tid >> 5, lane = tid & 31;
    const int g    = lane >> 2, tig = lane & 3;
    const int l8   = lane & 7, lq = lane >> 3;
    const int woff = warp * 16;
    const int bh   = blockIdx.y;
    const int q0   = blockIdx.x * QT;

    const size_t bhSP = (size_t)bh * S_LEN * P_DIM;
    const size_t bhPS = (size_t)bh * P_DIM * S_LEN;

    uint32_t aKh[2], aKl[2], aVh[2], aVl[2];
    #pragma unroll
    for (int b = 0; b < 2; b++) {
        aKh[b] = smem_u32(&Kh[b][l8][8 * lq]);
        aKl[b] = smem_u32(&Kl[b][l8][8 * lq]);
        aVh[b] = smem_u32(&Vth[b][l8][8 * lq]);
        aVl[b] = smem_u32(&Vtl[b][l8][8 * lq]);
    }

    #define LOAD_TILE(kt, b) do {                                               \
        int _k0 = (kt) * KN;                                                    \
        for (int i = tid; i < KN * 4; i += ATT) {                               \
            int r = i >> 2, c = (i & 3) * 8;                                    \
            cp16(smem_u32(&Kh[b][r][c]),                                        \
                 &g_kh[bhSP + (size_t)(_k0 + r) * P_DIM + c]);                  \
            cp16(smem_u32(&Kl[b][r][c]),                                        \
                 &g_kl[bhSP + (size_t)(_k0 + r) * P_DIM + c]);                  \
        }                                                                       \
        for (int i = tid; i < P_DIM * 8; i += ATT) {                            \
            int p = i >> 3, c = (i & 7) * 8;                                    \
            cp16(smem_u32(&Vth[b][p][c]),                                       \
                 &g_vth[bhPS + (size_t)p * S_LEN + _k0 + c]);                   \
            cp16(smem_u32(&Vtl[b][p][c]),                                       \
                 &g_vtl[bhPS + (size_t)p * S_LEN + _k0 + c]);                   \
        }                                                                       \
    } while (0)

    LOAD_TILE(0, 0);
    CP_COMMIT();

    const int r0g = q0 + woff + g;
    const size_t qb0 = bhSP + (size_t)r0g * P_DIM;
    const size_t qb1 = qb0 + 8 * P_DIM;
    uint32_t qh[2][4], ql[2][4];
    #pragma unroll
    for (int ks = 0; ks < 2; ks++) {
        int p0 = ks * 16 + 2 * tig;
        qh[ks][0] = *(const uint32_t*)&g_qh[qb0 + p0];
        qh[ks][1] = *(const uint32_t*)&g_qh[qb1 + p0];
        qh[ks][2] = *(const uint32_t*)&g_qh[qb0 + p0 + 8];
        qh[ks][3] = *(const uint32_t*)&g_qh[qb1 + p0 + 8];
        ql[ks][0] = *(const uint32_t*)&g_ql[qb0 + p0];
        ql[ks][1] = *(const uint32_t*)&g_ql[qb1 + p0];
        ql[ks][2] = *(const uint32_t*)&g_ql[qb0 + p0 + 8];
        ql[ks][3] = *(const uint32_t*)&g_ql[qb1 + p0 + 8];
    }

    float o[4][4] = {};
    float l0 = 0.f, l1 = 0.f;

    for (int kt = 0; kt < NKT; kt++) {
        const int buf = kt & 1;
        if (kt + 1 < NKT) {
            LOAD_TILE(kt + 1, buf ^ 1);
            CP_COMMIT();
            CP_WAIT(1);
        } else {
            CP_WAIT(0);
        }
        __syncthreads();

        uint32_t phi01[8], phi23[8], plo01[8], plo23[8];
        #pragma unroll
        for (int nt = 0; nt < 8; nt++) {
            uint32_t kh4[4], kl4[4];
            ldsm_x4(kh4, aKh[buf] + nt * (8 * 40 * 2));
            ldsm_x4(kl4, aKl[buf] + nt * (8 * 40 * 2));
            float c[4] = {0.f, 0.f, 0.f, 0.f};
            mma16816(c, qh[0][0], qh[0][1], qh[0][2], qh[0][3], kh4[0], kh4[1]);
            mma16816(c, ql[0][0], ql[0][1], ql[0][2], ql[0][3], kh4[0], kh4[1]);
            mma16816(c, qh[0][0], qh[0][1], qh[0][2], qh[0][3], kl4[0], kl4[1]);
            mma16816(c, qh[1][0], qh[1][1], qh[1][2], qh[1][3], kh4[2], kh4[3]);
            mma16816(c, ql[1][0], ql[1][1], ql[1][2], ql[1][3], kh4[2], kh4[3]);
            mma16816(c, qh[1][0], qh[1][1], qh[1][2], qh[1][3], kl4[2], kl4[3]);

            float e0 = ex2f(c[0]);
            float e1 = ex2f(c[1]);
            float e2 = ex2f(c[2]);
            float e3 = ex2f(c[3]);
            l0 += e0 + e1;
            l1 += e2 + e3;
            uint32_t ph01 = pack_bf16x2(e0, e1);
            uint32_t ph23 = pack_bf16x2(e2, e3);
            phi01[nt] = ph01;
            phi23[nt] = ph23;
            plo01[nt] = pack_bf16x2(e0 - __uint_as_float(ph01 << 16),
                                    e1 - __uint_as_float(ph01 & 0xffff0000u));
            plo23[nt] = pack_bf16x2(e2 - __uint_as_float(ph23 << 16),
                                    e3 - __uint_as_float(ph23 & 0xffff0000u));
        }

        #pragma unroll
        for (int n = 0; n < 4; n++) {
            uint32_t vhA[4], vhB[4], vlA[4], vlB[4];
            uint32_t base = n * (8 * 72 * 2);
            ldsm_x4(vhA, aVh[buf] + base);
            ldsm_x4(vhB, aVh[buf] + base + 64);
            ldsm_x4(vlA, aVl[buf] + base);
            ldsm_x4(vlB, aVl[buf] + base + 64);
            #pragma unroll
            for (int ks = 0; ks < 4; ks++) {
                uint32_t b0h = (ks < 2 ? vhA : vhB)[2 * (ks & 1)];
                uint32_t b1h = (ks < 2 ? vhA : vhB)[2 * (ks & 1) + 1];
                uint32_t b0l = (ks < 2 ? vlA : vlB)[2 * (ks & 1)];
                uint32_t b1l = (ks < 2 ? vlA : vlB)[2 * (ks & 1) + 1];
                uint32_t a0 = phi01[2 * ks], a1 = phi23[2 * ks];
                uint32_t a2 = phi01[2 * ks + 1], a3 = phi23[2 * ks + 1];
                mma16816(o[n], a0, a1, a2, a3, b0h, b1h);
                mma16816(o[n], a0, a1, a2, a3, b0l, b1l);
                mma16816(o[n], plo01[2 * ks], plo23[2 * ks],
                               plo01[2 * ks + 1], plo23[2 * ks + 1], b0h, b1h);
            }
        }
        __syncthreads();
    }

    l0 += __shfl_xor_sync(0xffffffffu, l0, 1);
    l0 += __shfl_xor_sync(0xffffffffu, l0, 2);
    l1 += __shfl_xor_sync(0xffffffffu, l1, 1);
    l1 += __shfl_xor_sync(0xffffffffu, l1, 2);
    const float inv0 = 1.0f / l0;
    const float inv1 = 1.0f / l1;

    const int b = bh >> 3, h = bh & 7;
    const int r1g = r0g + 8;
    #pragma unroll
    for (int n = 0; n < 4; n++) {
        int p = 8 * n + 2 * tig;
        {
            float w0 = o[n][0] * inv0, w1 = o[n][1] * inv0;
            size_t idx = ((size_t)b * S_LEN + r0g) * E_DIM + h * P_DIM + p;
            uint32_t ph = pack_bf16x2(w0, w1);
            *(uint32_t*)&g_oh[idx] = ph;
            *(uint32_t*)&g_ol[idx] = pack_bf16x2(w0 - __uint_as_float(ph << 16),
                                                 w1 - __uint_as_float(ph & 0xffff0000u));
        }
        {
            float w0 = o[n][2] * inv1, w1 = o[n][3] * inv1;
            size_t idx = ((size_t)b * S_LEN + r1g) * E_DIM + h * P_DIM + p;
            uint32_t ph = pack_bf16x2(w0, w1);
            *(uint32_t*)&g_oh[idx] = ph;
            *(uint32_t*)&g_ol[idx] = pack_bf16x2(w0 - __uint_as_float(ph << 16),
                                                 w1 - __uint_as_float(ph & 0xffff0000u));
        }
    }
}

extern "C" void kernel_launch(void* const* d_in, const int* in_sizes, int n_in,
                              void* d_out, int out_size)
{
    const float* x  = (const float*)d_in[0];
    const float* bq = (const float*)d_in[2];
    const float* bk = (const float*)d_in[4];
    const float* bv = (const float*)d_in[6];
    const float* bo = (const float*)d_in[8];
    float* out = (float*)d_out;

    static bool attr_set = false;
    if (!attr_set) {
        cudaFuncSetAttribute(qkv_mma_kernel,
            cudaFuncAttributeMaxDynamicSharedMemorySize, GEMM_SMEM_BYTES);
        cudaFuncSetAttribute(out_mma_kernel,
            cudaFuncAttributeMaxDynamicSharedMemorySize, GEMM_SMEM_BYTES);
        attr_set = true;
    }

    prep_x_kernel<<<M_ROWS * E_DIM / 1024, 256>>>(x);
    prep_w_kernel<<<dim3(8, 8, 4), 256>>>(
        (const float*)d_in[1], (const float*)d_in[3],
        (const float*)d_in[5], (const float*)d_in[7]);
    qkv_mma_kernel<<<dim3(27, 4, 3), 256, GEMM_SMEM_BYTES>>>(bq, bk, bv);
    attn_mma_kernel<<<dim3(18, 16), ATT>>>();
    out_mma_kernel<<<dim3(27, 4), 256, GEMM_SMEM_BYTES>>>(bo, out);
}